// round 2
// baseline (speedup 1.0000x reference)
#include <cuda_runtime.h>
#include <math.h>

#define NB 1024
#define NS 200
#define NH 256

// ---------------- scratch (device globals; no allocations allowed) ----------
static __device__ float g_att[NB * NS];                    // softmax attention [b][s]
static __device__ float g_gx[NS * NB * 768];               // precomputed x-part [s][b][768]
static __device__ float g_wxT[256 * 768];                  // x-part weights, k-major [k][i]
static __device__ float g_whru[256 * 512];                 // h-part (r,u) packed [(k>>2)][j][k&3]
static __device__ float g_whc[256 * 256];                  // h-part (c)  packed [(k>>2)][j][k&3]
static __device__ float g_wot[256 * 256];                  // Wo transposed packed [(k>>2)][j][k&3]

__device__ __forceinline__ float sigmoidf_(float x) { return 1.0f / (1.0f + expf(-x)); }

// ---------------- K0: weight repacking ---------------------------------------
__global__ void prep_kernel(const float* __restrict__ Wr, const float* __restrict__ Wu,
                            const float* __restrict__ Wc, const float* __restrict__ Wo)
{
    int idx = blockIdx.x * blockDim.x + threadIdx.x;
    if (idx < 196608) {
        // g_wxT[k][i] = W*[i][k]  (x-part: cols 0..255 of Wr/Wu/Wc)
        int k = idx / 768, i = idx - k * 768;
        float v;
        if (i < 256)      v = Wr[i * 512 + k];
        else if (i < 512) v = Wu[(i - 256) * 512 + k];
        else              v = Wc[(i - 512) * 512 + k];
        g_wxT[idx] = v;
    } else if (idx < 196608 + 131072) {
        int r = idx - 196608;
        int k = r / 512, j = r - k * 512;
        float v = (j < 256) ? Wr[j * 512 + 256 + k] : Wu[(j - 256) * 512 + 256 + k];
        g_whru[(k >> 2) * 2048 + j * 4 + (k & 3)] = v;
    } else if (idx < 196608 + 131072 + 65536) {
        int r = idx - (196608 + 131072);
        int k = r / 256, j = r - k * 256;
        g_whc[(k >> 2) * 1024 + j * 4 + (k & 3)] = Wc[j * 512 + 256 + k];
    } else if (idx < 196608 + 131072 + 131072) {
        int r = idx - (196608 + 131072 + 65536);
        int k = r / 256, j = r - k * 256;
        g_wot[(k >> 2) * 1024 + j * 4 + (k & 3)] = Wo[j * 256 + k];
    }
}

// ---------------- K1: attention softmax --------------------------------------
__global__ void __launch_bounds__(256) attn_kernel(const float* __restrict__ hist,
                                                   const float* __restrict__ tgt,
                                                   const int* __restrict__ mask)
{
    __shared__ float tg[256];
    __shared__ float lg[200];
    __shared__ float red[8];
    int b = blockIdx.x;
    int t = threadIdx.x;
    int lane = t & 31, w = t >> 5;
    tg[t] = tgt[b * 256 + t];
    __syncthreads();
    for (int s = w; s < 200; s += 8) {
        const float* hp = hist + ((size_t)(b * 200 + s)) * 256;
        float acc = 0.0f;
        #pragma unroll
        for (int i = 0; i < 8; i++) acc += hp[lane + 32 * i] * tg[lane + 32 * i];
        #pragma unroll
        for (int o = 16; o > 0; o >>= 1) acc += __shfl_xor_sync(0xffffffffu, acc, o);
        if (lane == 0)
            lg[s] = (mask[b * 200 + s] == 0) ? -1.0e9f : acc * 0.0625f; // 1/sqrt(256)
    }
    __syncthreads();
    float v = (t < 200) ? lg[t] : -3.0e38f;
    float m = v;
    #pragma unroll
    for (int o = 16; o > 0; o >>= 1) m = fmaxf(m, __shfl_xor_sync(0xffffffffu, m, o));
    if (lane == 0) red[w] = m;
    __syncthreads();
    if (t == 0) {
        float mm = red[0];
        for (int i = 1; i < 8; i++) mm = fmaxf(mm, red[i]);
        red[0] = mm;
    }
    __syncthreads();
    float mx = red[0];
    float e = (t < 200) ? expf(v - mx) : 0.0f;
    __syncthreads();
    float ssum = e;
    #pragma unroll
    for (int o = 16; o > 0; o >>= 1) ssum += __shfl_xor_sync(0xffffffffu, ssum, o);
    if (lane == 0) red[w] = ssum;
    __syncthreads();
    if (t == 0) {
        float tt = 0.0f;
        for (int i = 0; i < 8; i++) tt += red[i];
        red[0] = tt;
    }
    __syncthreads();
    if (t < 200) g_att[b * 200 + t] = e / red[0];
}

// ---------------- K2: Gx = hist @ WxT + bias  (M=204800,K=256,N=768) ---------
__global__ void __launch_bounds__(256) gx_gemm_kernel(const float* __restrict__ A,
                                                      const float* __restrict__ br,
                                                      const float* __restrict__ bu,
                                                      const float* __restrict__ bc)
{
    __shared__ __align__(16) float As[16 * 132];
    __shared__ __align__(16) float Bs[16 * 132];
    int m0 = blockIdx.x * 128;
    int n0 = blockIdx.y * 128;
    int t = threadIdx.x;
    int tx = t & 15, ty = t >> 4;
    float acc[8][8];
    #pragma unroll
    for (int i = 0; i < 8; i++)
        #pragma unroll
        for (int j = 0; j < 8; j++) acc[i][j] = 0.0f;

    int la_row = t >> 2;          // 0..63
    int la_c = (t & 3) * 4;       // k offset within chunk
    int lb_row = t >> 5;          // 0..7
    int lb_c = (t & 31) * 4;

    for (int kc = 0; kc < 256; kc += 16) {
        float4 a0 = *(const float4*)(A + (size_t)(m0 + la_row) * 256 + kc + la_c);
        float4 a1 = *(const float4*)(A + (size_t)(m0 + la_row + 64) * 256 + kc + la_c);
        float4 b0 = *(const float4*)(g_wxT + (kc + lb_row) * 768 + n0 + lb_c);
        float4 b1 = *(const float4*)(g_wxT + (kc + lb_row + 8) * 768 + n0 + lb_c);
        __syncthreads();
        As[(la_c + 0) * 132 + la_row] = a0.x;
        As[(la_c + 1) * 132 + la_row] = a0.y;
        As[(la_c + 2) * 132 + la_row] = a0.z;
        As[(la_c + 3) * 132 + la_row] = a0.w;
        As[(la_c + 0) * 132 + la_row + 64] = a1.x;
        As[(la_c + 1) * 132 + la_row + 64] = a1.y;
        As[(la_c + 2) * 132 + la_row + 64] = a1.z;
        As[(la_c + 3) * 132 + la_row + 64] = a1.w;
        *(float4*)&Bs[lb_row * 132 + lb_c] = b0;
        *(float4*)&Bs[(lb_row + 8) * 132 + lb_c] = b1;
        __syncthreads();
        #pragma unroll
        for (int k = 0; k < 16; k++) {
            float af[8], bf[8];
            *(float4*)(af)     = *(const float4*)&As[k * 132 + ty * 8];
            *(float4*)(af + 4) = *(const float4*)&As[k * 132 + ty * 8 + 4];
            *(float4*)(bf)     = *(const float4*)&Bs[k * 132 + tx * 8];
            *(float4*)(bf + 4) = *(const float4*)&Bs[k * 132 + tx * 8 + 4];
            #pragma unroll
            for (int i = 0; i < 8; i++)
                #pragma unroll
                for (int j = 0; j < 8; j++)
                    acc[i][j] += af[i] * bf[j];
        }
    }
    float bias[8];
    int nb = n0 + tx * 8;
    #pragma unroll
    for (int j = 0; j < 8; j++) {
        int n = nb + j;
        bias[j] = (n < 256) ? br[n] : (n < 512) ? bu[n - 256] : bc[n - 512];
    }
    #pragma unroll
    for (int i = 0; i < 8; i++) {
        int m = m0 + ty * 8 + i;
        int b = m / 200, s = m - b * 200;
        float* dst = g_gx + ((size_t)s * NB + b) * 768 + nb;
        float4 o0 = make_float4(acc[i][0] + bias[0], acc[i][1] + bias[1],
                                acc[i][2] + bias[2], acc[i][3] + bias[3]);
        float4 o1 = make_float4(acc[i][4] + bias[4], acc[i][5] + bias[5],
                                acc[i][6] + bias[6], acc[i][7] + bias[7]);
        *(float4*)dst = o0;
        *(float4*)(dst + 4) = o1;
    }
}

// ---------------- K3: persistent sequential GRU scan -------------------------
// 128 CTAs x 512 threads; CTA owns 8 batch rows, h in SMEM, no cross-CTA comm.
__global__ void __launch_bounds__(512, 1) gru_kernel(const int* __restrict__ mask,
                                                     const float* __restrict__ bo,
                                                     float* __restrict__ out)
{
    __shared__ __align__(16) float h_s[8][256];
    __shared__ __align__(16) float rh_s[8][256];
    __shared__ float u_s[8][256];
    __shared__ float a_s[8];
    __shared__ int   m_s[8];
    int b0 = blockIdx.x * 8;
    int t = threadIdx.x;
    int jc = t & 255;
    int rbase = (t >> 8) * 4;

    for (int i = t; i < 8 * 256; i += 512) (&h_s[0][0])[i] = 0.0f;
    float pool[4];
    #pragma unroll
    for (int i = 0; i < 4; i++) pool[i] = -3.0e38f;
    __syncthreads();

    for (int s = 0; s < 200; s++) {
        if (t < 8) {
            a_s[t] = g_att[(b0 + t) * NS + s];
            m_s[t] = mask[(b0 + t) * NS + s];
        }
        // GEMM1: pre_{r,u}[rb][t] = sum_k h[rb][k] * Whru[k][t]
        float acc[8];
        #pragma unroll
        for (int i = 0; i < 8; i++) acc[i] = 0.0f;
        #pragma unroll 4
        for (int k4 = 0; k4 < 64; k4++) {
            float4 wv = *(const float4*)(g_whru + k4 * 2048 + t * 4);
            #pragma unroll
            for (int rb = 0; rb < 8; rb++) {
                float4 hv = *(const float4*)(&h_s[rb][k4 * 4]);
                acc[rb] += hv.x * wv.x + hv.y * wv.y + hv.z * wv.z + hv.w * wv.w;
            }
        }
        const float* gxp = g_gx + ((size_t)s * NB + b0) * 768 + t;
        if (t < 256) {
            #pragma unroll
            for (int rb = 0; rb < 8; rb++) {
                float r = sigmoidf_(acc[rb] + gxp[rb * 768]);
                rh_s[rb][t] = r * h_s[rb][t];
            }
        } else {
            #pragma unroll
            for (int rb = 0; rb < 8; rb++)
                u_s[rb][jc] = sigmoidf_(acc[rb] + gxp[rb * 768]);
        }
        __syncthreads();
        // GEMM2: pre_c[rb][jc] = sum_k rh[rb][k] * Whc[k][jc]   (4 rows per thread)
        float acc2[4];
        #pragma unroll
        for (int i = 0; i < 4; i++) acc2[i] = 0.0f;
        #pragma unroll 4
        for (int k4 = 0; k4 < 64; k4++) {
            float4 wv = *(const float4*)(g_whc + k4 * 1024 + jc * 4);
            #pragma unroll
            for (int i = 0; i < 4; i++) {
                float4 hv = *(const float4*)(&rh_s[rbase + i][k4 * 4]);
                acc2[i] += hv.x * wv.x + hv.y * wv.y + hv.z * wv.z + hv.w * wv.w;
            }
        }
        const float* gxp2 = g_gx + ((size_t)s * NB + b0 + rbase) * 768 + 512 + jc;
        #pragma unroll
        for (int i = 0; i < 4; i++) {
            int rb = rbase + i;
            float c = tanhf(acc2[i] + gxp2[i * 768]);
            float uu = a_s[rb] * u_s[rb][jc];
            float hn = (1.0f - uu) * h_s[rb][jc] + uu * c;
            h_s[rb][jc] = hn;
            pool[i] = fmaxf(pool[i], m_s[rb] ? hn : 0.0f);
        }
        __syncthreads();
    }

    // epilogue: last-h + masked-max-pool @ Wo^T + bo
    #pragma unroll
    for (int i = 0; i < 4; i++) rh_s[rbase + i][jc] = pool[i];
    __syncthreads();
    if (t < 256) {
        #pragma unroll
        for (int rb = 0; rb < 8; rb++)
            out[(size_t)(b0 + rb) * 512 + t] = h_s[rb][t];
        float acc3[8];
        #pragma unroll
        for (int i = 0; i < 8; i++) acc3[i] = 0.0f;
        #pragma unroll 4
        for (int k4 = 0; k4 < 64; k4++) {
            float4 wv = *(const float4*)(g_wot + k4 * 1024 + t * 4);
            #pragma unroll
            for (int rb = 0; rb < 8; rb++) {
                float4 hv = *(const float4*)(&rh_s[rb][k4 * 4]);
                acc3[rb] += hv.x * wv.x + hv.y * wv.y + hv.z * wv.z + hv.w * wv.w;
            }
        }
        float bb = bo[t];
        #pragma unroll
        for (int rb = 0; rb < 8; rb++)
            out[(size_t)(b0 + rb) * 512 + 256 + t] = acc3[rb] + bb;
    }
}

// ---------------- launch ------------------------------------------------------
extern "C" void kernel_launch(void* const* d_in, const int* in_sizes, int n_in,
                              void* d_out, int out_size)
{
    const float* hist = (const float*)d_in[0];
    const float* tgt  = (const float*)d_in[1];
    const int*   mask = (const int*)d_in[2];
    const float* Wr   = (const float*)d_in[3];
    const float* br   = (const float*)d_in[4];
    const float* Wu   = (const float*)d_in[5];
    const float* bu   = (const float*)d_in[6];
    const float* Wc   = (const float*)d_in[7];
    const float* bc   = (const float*)d_in[8];
    const float* Wo   = (const float*)d_in[9];
    const float* bo   = (const float*)d_in[10];
    float* out = (float*)d_out;

    prep_kernel<<<1792, 256>>>(Wr, Wu, Wc, Wo);
    attn_kernel<<<NB, 256>>>(hist, tgt, mask);
    gx_gemm_kernel<<<dim3(1600, 6), 256>>>(hist, br, bu, bc);
    gru_kernel<<<128, 512>>>(mask, bo, out);
}

// round 5
// speedup vs baseline: 1.1629x; 1.1629x over previous
#include <cuda_runtime.h>
#include <cuda_bf16.h>
#include <cstdint>
#include <math.h>

#define NB 1024
#define NS 200
#define NH 256
#define KTOT 768

// ---------------- scratch (device globals; no allocations allowed) ----------
static __device__ float g_att[NB * NS];                       // softmax attention [b][s]
static __device__ float g_gx[(size_t)NS * NB * 768];          // x-part preact [s][b][768]
static __device__ float g_whru[256 * 512];                    // h-part (r,u) packed
static __device__ float g_whc[256 * 256];                     // h-part (c) packed
static __device__ float g_wot[256 * 256];                     // Wo^T packed
static __device__ __nv_bfloat16 g_abf[(size_t)NB * NS * KTOT]; // A' = [Ah|Ah|Al] [m][768]
static __device__ __nv_bfloat16 g_bbf[768 * KTOT];             // B' = [Bh|Bl|Bh] [n][768]

__device__ __forceinline__ float sigmoidf_(float x) { return 1.0f / (1.0f + expf(-x)); }

__device__ __forceinline__ uint32_t smem_u32(const void* p) {
    uint32_t a;
    asm("{ .reg .u64 t; cvta.to.shared.u64 t, %1; cvt.u32.u64 %0, t; }" : "=r"(a) : "l"(p));
    return a;
}

#define CP_ASYNC16(dst, src) \
    asm volatile("cp.async.cg.shared.global [%0], [%1], 16;" :: "r"(dst), "l"(src))
#define CP_COMMIT() asm volatile("cp.async.commit_group;" ::: "memory")
#define CP_WAIT0()  asm volatile("cp.async.wait_group 0;" ::: "memory")
#define CP_WAIT1()  asm volatile("cp.async.wait_group 1;" ::: "memory")

#define LDSM4(r, addr)                                                            \
    asm volatile("ldmatrix.sync.aligned.m8n8.x4.shared.b16 {%0,%1,%2,%3}, [%4];"  \
                 : "=r"((r)[0]), "=r"((r)[1]), "=r"((r)[2]), "=r"((r)[3])         \
                 : "r"(addr))

#define MMA16816(d, a, b0, b1)                                                    \
    asm volatile("mma.sync.aligned.m16n8k16.row.col.f32.bf16.bf16.f32 "           \
                 "{%0,%1,%2,%3}, {%4,%5,%6,%7}, {%8,%9}, {%0,%1,%2,%3};"          \
                 : "+f"((d)[0]), "+f"((d)[1]), "+f"((d)[2]), "+f"((d)[3])         \
                 : "r"((a)[0]), "r"((a)[1]), "r"((a)[2]), "r"((a)[3]),            \
                   "r"(b0), "r"(b1))

// ---------------- K0a: weight repacking --------------------------------------
__global__ void prepw_kernel(const float* __restrict__ Wr, const float* __restrict__ Wu,
                             const float* __restrict__ Wc, const float* __restrict__ Wo)
{
    int idx = blockIdx.x * blockDim.x + threadIdx.x;
    if (idx < 196608) {
        // x-part weights -> B' = [Bh | Bl | Bh], [n][k] k-major
        int n = idx >> 8, k = idx & 255;
        float v;
        if (n < 256)      v = Wr[n * 512 + k];
        else if (n < 512) v = Wu[(n - 256) * 512 + k];
        else              v = Wc[(n - 512) * 512 + k];
        __nv_bfloat16 hi = __float2bfloat16(v);
        __nv_bfloat16 lo = __float2bfloat16(v - __bfloat162float(hi));
        g_bbf[(size_t)n * KTOT + k]       = hi;
        g_bbf[(size_t)n * KTOT + 256 + k] = lo;
        g_bbf[(size_t)n * KTOT + 512 + k] = hi;
    } else if (idx < 196608 + 131072) {
        int r = idx - 196608;
        int k = r / 512, j = r - k * 512;
        float v = (j < 256) ? Wr[j * 512 + 256 + k] : Wu[(j - 256) * 512 + 256 + k];
        g_whru[(k >> 2) * 2048 + j * 4 + (k & 3)] = v;
    } else if (idx < 196608 + 131072 + 65536) {
        int r = idx - (196608 + 131072);
        int k = r / 256, j = r - k * 256;
        g_whc[(k >> 2) * 1024 + j * 4 + (k & 3)] = Wc[j * 512 + 256 + k];
    } else if (idx < 196608 + 131072 + 131072) {
        int r = idx - (196608 + 131072 + 65536);
        int k = r / 256, j = r - k * 256;
        g_wot[(k >> 2) * 1024 + j * 4 + (k & 3)] = Wo[j * 256 + k];
    }
}

// ---------------- K0b: hist -> A' = [Ah | Ah | Al] ----------------------------
__global__ void __launch_bounds__(256) prepa_kernel(const float* __restrict__ hist)
{
    size_t i = (size_t)blockIdx.x * 256 + threadIdx.x;   // 13,107,200 threads x 4 elems
    int m = (int)(i >> 6);
    int kq = ((int)i & 63) * 4;
    float4 v = *(const float4*)(hist + (size_t)m * 256 + kq);
    float x[4] = {v.x, v.y, v.z, v.w};
    __nv_bfloat16 h[4], l[4];
    #pragma unroll
    for (int j = 0; j < 4; j++) {
        h[j] = __float2bfloat16(x[j]);
        l[j] = __float2bfloat16(x[j] - __bfloat162float(h[j]));
    }
    uint32_t hi01 = (uint32_t)__bfloat16_as_ushort(h[0]) | ((uint32_t)__bfloat16_as_ushort(h[1]) << 16);
    uint32_t hi23 = (uint32_t)__bfloat16_as_ushort(h[2]) | ((uint32_t)__bfloat16_as_ushort(h[3]) << 16);
    uint32_t lo01 = (uint32_t)__bfloat16_as_ushort(l[0]) | ((uint32_t)__bfloat16_as_ushort(l[1]) << 16);
    uint32_t lo23 = (uint32_t)__bfloat16_as_ushort(l[2]) | ((uint32_t)__bfloat16_as_ushort(l[3]) << 16);
    __nv_bfloat16* row = g_abf + (size_t)m * KTOT + kq;
    *(uint2*)(row)       = make_uint2(hi01, hi23);
    *(uint2*)(row + 256) = make_uint2(hi01, hi23);
    *(uint2*)(row + 512) = make_uint2(lo01, lo23);
}

// ---------------- K1: attention softmax --------------------------------------
__global__ void __launch_bounds__(256) attn_kernel(const float* __restrict__ hist,
                                                   const float* __restrict__ tgt,
                                                   const int* __restrict__ mask)
{
    __shared__ float tg[256];
    __shared__ float lg[200];
    __shared__ float red[8];
    int b = blockIdx.x;
    int t = threadIdx.x;
    int lane = t & 31, w = t >> 5;
    tg[t] = tgt[b * 256 + t];
    __syncthreads();
    for (int s = w; s < 200; s += 8) {
        const float* hp = hist + ((size_t)(b * 200 + s)) * 256;
        float acc = 0.0f;
        #pragma unroll
        for (int i = 0; i < 8; i++) acc += hp[lane + 32 * i] * tg[lane + 32 * i];
        #pragma unroll
        for (int o = 16; o > 0; o >>= 1) acc += __shfl_xor_sync(0xffffffffu, acc, o);
        if (lane == 0)
            lg[s] = (mask[b * 200 + s] == 0) ? -1.0e9f : acc * 0.0625f;
    }
    __syncthreads();
    float v = (t < 200) ? lg[t] : -3.0e38f;
    float m = v;
    #pragma unroll
    for (int o = 16; o > 0; o >>= 1) m = fmaxf(m, __shfl_xor_sync(0xffffffffu, m, o));
    if (lane == 0) red[w] = m;
    __syncthreads();
    if (t == 0) {
        float mm = red[0];
        for (int i = 1; i < 8; i++) mm = fmaxf(mm, red[i]);
        red[0] = mm;
    }
    __syncthreads();
    float mx = red[0];
    float e = (t < 200) ? expf(v - mx) : 0.0f;
    __syncthreads();
    float ssum = e;
    #pragma unroll
    for (int o = 16; o > 0; o >>= 1) ssum += __shfl_xor_sync(0xffffffffu, ssum, o);
    if (lane == 0) red[w] = ssum;
    __syncthreads();
    if (t == 0) {
        float tt = 0.0f;
        for (int i = 0; i < 8; i++) tt += red[i];
        red[0] = tt;
    }
    __syncthreads();
    if (t < 200) g_att[b * 200 + t] = e / red[0];
}

// ---------------- K2: Gx GEMM via mma.sync bf16 (M=204800,N=768,K=768) --------
// CTA tile 128x128, 8 warps (warp tile 64x32), cp.async double-buffered K=64 chunks.
static constexpr int GX_TILE_BYTES = 16384;                       // 128 rows x 128B
static constexpr int GX_BUF_BYTES  = 2 * GX_TILE_BYTES;           // A + B
static constexpr int GX_SMEM_BYTES = 1024 + 2 * GX_BUF_BYTES;     // hdr + 2 buffers

__global__ void __launch_bounds__(256, 1) gx_mma_kernel(const float* __restrict__ br,
                                                        const float* __restrict__ bu,
                                                        const float* __restrict__ bc)
{
    extern __shared__ char sm[];
    float* bias_s = (float*)sm;
    char* tiles = sm + 1024;
    uint32_t tiles_u = smem_u32(tiles);

    int t = threadIdx.x;
    int lane = t & 31, wid = t >> 5;
    int n0 = blockIdx.x * 128;        // n fastest -> A-tile L2 reuse
    int m0 = blockIdx.y * 128;

    if (t < 128) {
        int n = n0 + t;
        bias_s[t] = (n < 256) ? br[n] : (n < 512) ? bu[n - 256] : bc[n - 512];
    }

    // ---- cp.async loader setup: 128x64 bf16 tile = 1024 16B units, 256 thr x 4 reps
    int lrow = t >> 3;                // 0..31
    int lc16 = t & 7;                 // 16B unit within row
    const __nv_bfloat16* gA = g_abf + (size_t)(m0 + lrow) * KTOT + lc16 * 8;
    const __nv_bfloat16* gB = g_bbf + (size_t)(n0 + lrow) * KTOT + lc16 * 8;
    uint32_t sA[4], sB[4];
    #pragma unroll
    for (int r = 0; r < 4; r++) {
        uint32_t off = (uint32_t)((lrow + r * 32) * 128 + lc16 * 16);
        off ^= (off >> 3) & 0x70;                    // SW128
        sA[r] = tiles_u + off;
        sB[r] = tiles_u + GX_TILE_BYTES + off;
    }

    // ---- ldmatrix address precompute (R + (C ^ X) trick)
    int wm = (wid >> 2) * 64;         // warp m offset (2 rows of warps)
    int wn = (wid & 3) * 32;          // warp n offset (4 cols of warps)
    uint32_t aR[4], aX[4], bR[2], bX[2];
    #pragma unroll
    for (int mf = 0; mf < 4; mf++) {
        uint32_t R = (uint32_t)(wm + mf * 16 + (lane & 15)) * 128;
        aR[mf] = R; aX[mf] = (R >> 3) & 0x70;
    }
    #pragma unroll
    for (int nf2 = 0; nf2 < 2; nf2++) {
        uint32_t R = (uint32_t)(wn + nf2 * 16 + (lane & 15)) * 128;
        bR[nf2] = R; bX[nf2] = (R >> 3) & 0x70;
    }
    uint32_t Ckl = ((uint32_t)(lane >> 4)) << 4;     // k-half byte offset

    float d[4][4][4];
    #pragma unroll
    for (int i = 0; i < 4; i++)
        #pragma unroll
        for (int j = 0; j < 4; j++)
            #pragma unroll
            for (int r = 0; r < 4; r++) d[i][j][r] = 0.0f;

    // prologue
    #pragma unroll
    for (int r = 0; r < 4; r++) {
        CP_ASYNC16(sA[r], gA + (size_t)(r * 32) * KTOT);
        CP_ASYNC16(sB[r], gB + (size_t)(r * 32) * KTOT);
    }
    CP_COMMIT();

    const int NCHUNK = KTOT / 64;   // 12
    for (int c = 0; c < NCHUNK; c++) {
        int buf = c & 1;
        if (c + 1 < NCHUNK) {
            uint32_t bo = (uint32_t)((buf ^ 1) * GX_BUF_BYTES);
            int kc = (c + 1) * 64;
            #pragma unroll
            for (int r = 0; r < 4; r++) {
                CP_ASYNC16(sA[r] + bo, gA + (size_t)(r * 32) * KTOT + kc);
                CP_ASYNC16(sB[r] + bo, gB + (size_t)(r * 32) * KTOT + kc);
            }
            CP_COMMIT();
            CP_WAIT1();
        } else {
            CP_WAIT0();
        }
        __syncthreads();
        uint32_t abase = tiles_u + (uint32_t)(buf * GX_BUF_BYTES);
        uint32_t bbase = abase + GX_TILE_BYTES;
        #pragma unroll
        for (int ks = 0; ks < 4; ks++) {
            uint32_t C = (uint32_t)(ks * 32) + Ckl;
            uint32_t a[4][4], bb[2][4];
            #pragma unroll
            for (int mf = 0; mf < 4; mf++)
                LDSM4(a[mf], abase + aR[mf] + (C ^ aX[mf]));
            #pragma unroll
            for (int nf2 = 0; nf2 < 2; nf2++)
                LDSM4(bb[nf2], bbase + bR[nf2] + (C ^ bX[nf2]));
            #pragma unroll
            for (int mf = 0; mf < 4; mf++) {
                #pragma unroll
                for (int nf = 0; nf < 4; nf++) {
                    uint32_t b0 = bb[nf >> 1][nf & 1];
                    uint32_t b1 = bb[nf >> 1][(nf & 1) + 2];
                    MMA16816(d[mf][nf], a[mf], b0, b1);
                }
            }
        }
        __syncthreads();
    }

    // ---- epilogue: bias add + permuted store to g_gx[s][b][n]
    int groupID = lane >> 2;
    int tc = (lane & 3) * 2;
    #pragma unroll
    for (int mf = 0; mf < 4; mf++) {
        #pragma unroll
        for (int half = 0; half < 2; half++) {
            int m = m0 + wm + mf * 16 + groupID + half * 8;
            int b = m / 200, s = m - b * 200;
            float* dst = g_gx + ((size_t)s * NB + b) * 768 + n0 + wn;
            #pragma unroll
            for (int nf = 0; nf < 4; nf++) {
                float2 bi = *(float2*)&bias_s[wn + nf * 8 + tc];
                float2 o = make_float2(d[mf][nf][half * 2 + 0] + bi.x,
                                       d[mf][nf][half * 2 + 1] + bi.y);
                *(float2*)(dst + nf * 8 + tc) = o;
            }
        }
    }
}

// ---------------- K3: persistent sequential GRU scan -------------------------
__global__ void __launch_bounds__(512, 1) gru_kernel(const int* __restrict__ mask,
                                                     const float* __restrict__ bo,
                                                     float* __restrict__ out)
{
    __shared__ __align__(16) float h_s[8][256];
    __shared__ __align__(16) float rh_s[8][256];
    __shared__ float u_s[8][256];
    __shared__ float a_s[8];
    __shared__ int   m_s[8];
    int b0 = blockIdx.x * 8;
    int t = threadIdx.x;
    int jc = t & 255;
    int rbase = (t >> 8) * 4;

    for (int i = t; i < 8 * 256; i += 512) (&h_s[0][0])[i] = 0.0f;
    float pool[4];
    #pragma unroll
    for (int i = 0; i < 4; i++) pool[i] = -3.0e38f;
    __syncthreads();

    for (int s = 0; s < 200; s++) {
        if (t < 8) {
            a_s[t] = g_att[(b0 + t) * NS + s];
            m_s[t] = mask[(b0 + t) * NS + s];
        }
        float acc[8];
        #pragma unroll
        for (int i = 0; i < 8; i++) acc[i] = 0.0f;
        #pragma unroll 4
        for (int k4 = 0; k4 < 64; k4++) {
            float4 wv = *(const float4*)(g_whru + k4 * 2048 + t * 4);
            #pragma unroll
            for (int rb = 0; rb < 8; rb++) {
                float4 hv = *(const float4*)(&h_s[rb][k4 * 4]);
                acc[rb] += hv.x * wv.x + hv.y * wv.y + hv.z * wv.z + hv.w * wv.w;
            }
        }
        const float* gxp = g_gx + ((size_t)s * NB + b0) * 768 + t;
        if (t < 256) {
            #pragma unroll
            for (int rb = 0; rb < 8; rb++) {
                float r = sigmoidf_(acc[rb] + gxp[rb * 768]);
                rh_s[rb][t] = r * h_s[rb][t];
            }
        } else {
            #pragma unroll
            for (int rb = 0; rb < 8; rb++)
                u_s[rb][jc] = sigmoidf_(acc[rb] + gxp[rb * 768]);
        }
        __syncthreads();
        float acc2[4];
        #pragma unroll
        for (int i = 0; i < 4; i++) acc2[i] = 0.0f;
        #pragma unroll 4
        for (int k4 = 0; k4 < 64; k4++) {
            float4 wv = *(const float4*)(g_whc + k4 * 1024 + jc * 4);
            #pragma unroll
            for (int i = 0; i < 4; i++) {
                float4 hv = *(const float4*)(&rh_s[rbase + i][k4 * 4]);
                acc2[i] += hv.x * wv.x + hv.y * wv.y + hv.z * wv.z + hv.w * wv.w;
            }
        }
        const float* gxp2 = g_gx + ((size_t)s * NB + b0 + rbase) * 768 + 512 + jc;
        #pragma unroll
        for (int i = 0; i < 4; i++) {
            int rb = rbase + i;
            float c = tanhf(acc2[i] + gxp2[i * 768]);
            float uu = a_s[rb] * u_s[rb][jc];
            float hn = (1.0f - uu) * h_s[rb][jc] + uu * c;
            h_s[rb][jc] = hn;
            pool[i] = fmaxf(pool[i], m_s[rb] ? hn : 0.0f);
        }
        __syncthreads();
    }

    #pragma unroll
    for (int i = 0; i < 4; i++) rh_s[rbase + i][jc] = pool[i];
    __syncthreads();
    if (t < 256) {
        #pragma unroll
        for (int rb = 0; rb < 8; rb++)
            out[(size_t)(b0 + rb) * 512 + t] = h_s[rb][t];
        float acc3[8];
        #pragma unroll
        for (int i = 0; i < 8; i++) acc3[i] = 0.0f;
        #pragma unroll 4
        for (int k4 = 0; k4 < 64; k4++) {
            float4 wv = *(const float4*)(g_wot + k4 * 1024 + t * 4);
            #pragma unroll
            for (int rb = 0; rb < 8; rb++) {
                float4 hv = *(const float4*)(&rh_s[rb][k4 * 4]);
                acc3[rb] += hv.x * wv.x + hv.y * wv.y + hv.z * wv.z + hv.w * wv.w;
            }
        }
        float bb = bo[t];
        #pragma unroll
        for (int rb = 0; rb < 8; rb++)
            out[(size_t)(b0 + rb) * 512 + 256 + t] = acc3[rb] + bb;
    }
}

// ---------------- launch ------------------------------------------------------
extern "C" void kernel_launch(void* const* d_in, const int* in_sizes, int n_in,
                              void* d_out, int out_size)
{
    const float* hist = (const float*)d_in[0];
    const float* tgt  = (const float*)d_in[1];
    const int*   mask = (const int*)d_in[2];
    const float* Wr   = (const float*)d_in[3];
    const float* br   = (const float*)d_in[4];
    const float* Wu   = (const float*)d_in[5];
    const float* bu   = (const float*)d_in[6];
    const float* Wc   = (const float*)d_in[7];
    const float* bc   = (const float*)d_in[8];
    const float* Wo   = (const float*)d_in[9];
    const float* bo   = (const float*)d_in[10];
    float* out = (float*)d_out;

    cudaFuncSetAttribute(gx_mma_kernel, cudaFuncAttributeMaxDynamicSharedMemorySize,
                         GX_SMEM_BYTES);

    prepw_kernel<<<1792, 256>>>(Wr, Wu, Wc, Wo);
    prepa_kernel<<<51200, 256>>>(hist);
    attn_kernel<<<NB, 256>>>(hist, tgt, mask);
    gx_mma_kernel<<<dim3(6, 1600), 256, GX_SMEM_BYTES>>>(br, bu, bc);
    gru_kernel<<<128, 512>>>(mask, bo, out);
}

// round 7
// speedup vs baseline: 1.3121x; 1.1283x over previous
#include <cuda_runtime.h>
#include <cuda_bf16.h>
#include <cstdint>
#include <math.h>

#define NB 1024
#define NS 200
#define NH 256
#define KTOT 768

// ---------------- scratch (device globals; no allocations allowed) ----------
static __device__ float g_att[NB * NS];                        // softmax attention [b][s]
static __device__ float g_gx[(size_t)NS * NB * 768];           // x-part preact [s][b][768]
static __device__ __nv_bfloat16 g_abf[(size_t)NB * NS * KTOT]; // A' = [Ah|Ah|Al] [m][768]
static __device__ __nv_bfloat16 g_bbf[768 * KTOT];             // B' = [Bh|Bl|Bh] [n][768]
static __device__ __nv_bfloat16 g_wruf[512 * 768];             // Whru' frag-layout (F=8)
static __device__ __nv_bfloat16 g_wcf[256 * 768];              // Whc'  frag-layout (F=4)

__device__ __forceinline__ float sig_(float x)  { return 1.0f / (1.0f + expf(-x)); }

__device__ __forceinline__ uint32_t smem_u32(const void* p) {
    uint32_t a;
    asm("{ .reg .u64 t; cvta.to.shared.u64 t, %1; cvt.u32.u64 %0, t; }" : "=r"(a) : "l"(p));
    return a;
}

#define CP_ASYNC16(dst, src) \
    asm volatile("cp.async.cg.shared.global [%0], [%1], 16;" :: "r"(dst), "l"(src))
#define CP_COMMIT() asm volatile("cp.async.commit_group;" ::: "memory")
#define CP_WAIT0()  asm volatile("cp.async.wait_group 0;" ::: "memory")
#define CP_WAIT1()  asm volatile("cp.async.wait_group 1;" ::: "memory")

#define LDSM4(r, addr)                                                            \
    asm volatile("ldmatrix.sync.aligned.m8n8.x4.shared.b16 {%0,%1,%2,%3}, [%4];"  \
                 : "=r"((r)[0]), "=r"((r)[1]), "=r"((r)[2]), "=r"((r)[3])         \
                 : "r"(addr))

#define MMA16816(d, a, b0, b1)                                                    \
    asm volatile("mma.sync.aligned.m16n8k16.row.col.f32.bf16.bf16.f32 "           \
                 "{%0,%1,%2,%3}, {%4,%5,%6,%7}, {%8,%9}, {%0,%1,%2,%3};"          \
                 : "+f"((d)[0]), "+f"((d)[1]), "+f"((d)[2]), "+f"((d)[3])         \
                 : "r"((a)[0]), "r"((a)[1]), "r"((a)[2]), "r"((a)[3]),            \
                   "r"(b0), "r"(b1))

// byte offset of weight element (n,k) in per-warp fragment layout (F frags/warp)
__device__ __forceinline__ uint32_t frag_off(int n, int k, int F, int slice_shift) {
    int w = n >> slice_shift;
    int f = (n >> 3) & (F - 1);
    int r = n & 7;
    int t2 = k >> 5;
    int th = (k >> 4) & 1;
    int kk = k & 15;
    int lane = (r << 2) | ((kk & 7) >> 1);
    int byte = (th << 3) | (((kk >> 3) & 1) << 2) | ((kk & 1) << 1);
    return (uint32_t)(((((w * F + f) * 24 + t2) * 32 + lane) << 4) + byte);
}

// swizzled byte offset within a 32x768-bf16 A-tile (1536B rows)
__device__ __forceinline__ uint32_t a_off(int m, int k) {
    int seg = k >> 3;
    int segs = (seg & ~7) | ((seg ^ m) & 7);
    return (uint32_t)(m * 1536 + segs * 16 + (k & 7) * 2);
}

__device__ __forceinline__ void bf16split(float x, __nv_bfloat16& h, __nv_bfloat16& l) {
    h = __float2bfloat16(x);
    l = __float2bfloat16(x - __bfloat162float(h));
}

// ---------------- K0a: weight packing ----------------------------------------
__global__ void prepw_kernel(const float* __restrict__ Wr, const float* __restrict__ Wu,
                             const float* __restrict__ Wc)
{
    int idx = blockIdx.x * blockDim.x + threadIdx.x;
    if (idx < 196608) {
        // gx B' = [Bh | Bl | Bh], [n][k] k-major (x-part cols 0..255)
        int n = idx >> 8, k = idx & 255;
        float v;
        if (n < 256)      v = Wr[n * 512 + k];
        else if (n < 512) v = Wu[(n - 256) * 512 + k];
        else              v = Wc[(n - 512) * 512 + k];
        __nv_bfloat16 hi, lo; bf16split(v, hi, lo);
        g_bbf[(size_t)n * KTOT + k]       = hi;
        g_bbf[(size_t)n * KTOT + 256 + k] = lo;
        g_bbf[(size_t)n * KTOT + 512 + k] = hi;
    } else if (idx < 196608 + 393216) {
        // Whru' fragment layout, K-concat [hi | lo | hi], h-part cols 256..511
        int e = idx - 196608;
        int n = e / 768, k = e - n * 768;
        int kk = k & 255;
        float v = (n < 256) ? Wr[n * 512 + 256 + kk] : Wu[(n - 256) * 512 + 256 + kk];
        __nv_bfloat16 hi, lo; bf16split(v, hi, lo);
        __nv_bfloat16 val = (k < 256) ? hi : (k < 512 ? lo : hi);
        *(__nv_bfloat16*)((char*)g_wruf + frag_off(n, k, 8, 6)) = val;
    } else if (idx < 196608 + 393216 + 196608) {
        int e = idx - 589824;
        int n = e / 768, k = e - n * 768;
        int kk = k & 255;
        float v = Wc[n * 512 + 256 + kk];
        __nv_bfloat16 hi, lo; bf16split(v, hi, lo);
        __nv_bfloat16 val = (k < 256) ? hi : (k < 512 ? lo : hi);
        *(__nv_bfloat16*)((char*)g_wcf + frag_off(n, k, 4, 5)) = val;
    }
}

// ---------------- K0b: hist -> A' = [Ah | Ah | Al] ----------------------------
__global__ void __launch_bounds__(256) prepa_kernel(const float* __restrict__ hist)
{
    size_t i = (size_t)blockIdx.x * 256 + threadIdx.x;
    int m = (int)(i >> 6);
    int kq = ((int)i & 63) * 4;
    float4 v = *(const float4*)(hist + (size_t)m * 256 + kq);
    float x[4] = {v.x, v.y, v.z, v.w};
    __nv_bfloat16 h[4], l[4];
    #pragma unroll
    for (int j = 0; j < 4; j++) bf16split(x[j], h[j], l[j]);
    uint32_t hi01 = (uint32_t)__bfloat16_as_ushort(h[0]) | ((uint32_t)__bfloat16_as_ushort(h[1]) << 16);
    uint32_t hi23 = (uint32_t)__bfloat16_as_ushort(h[2]) | ((uint32_t)__bfloat16_as_ushort(h[3]) << 16);
    uint32_t lo01 = (uint32_t)__bfloat16_as_ushort(l[0]) | ((uint32_t)__bfloat16_as_ushort(l[1]) << 16);
    uint32_t lo23 = (uint32_t)__bfloat16_as_ushort(l[2]) | ((uint32_t)__bfloat16_as_ushort(l[3]) << 16);
    __nv_bfloat16* row = g_abf + (size_t)m * KTOT + kq;
    *(uint2*)(row)       = make_uint2(hi01, hi23);
    *(uint2*)(row + 256) = make_uint2(hi01, hi23);
    *(uint2*)(row + 512) = make_uint2(lo01, lo23);
}

// ---------------- K1: attention softmax --------------------------------------
__global__ void __launch_bounds__(256) attn_kernel(const float* __restrict__ hist,
                                                   const float* __restrict__ tgt,
                                                   const int* __restrict__ mask)
{
    __shared__ float tg[256];
    __shared__ float lg[200];
    __shared__ float red[8];
    int b = blockIdx.x;
    int t = threadIdx.x;
    int lane = t & 31, w = t >> 5;
    tg[t] = tgt[b * 256 + t];
    __syncthreads();
    for (int s = w; s < 200; s += 8) {
        const float* hp = hist + ((size_t)(b * 200 + s)) * 256;
        float acc = 0.0f;
        #pragma unroll
        for (int i = 0; i < 8; i++) acc += hp[lane + 32 * i] * tg[lane + 32 * i];
        #pragma unroll
        for (int o = 16; o > 0; o >>= 1) acc += __shfl_xor_sync(0xffffffffu, acc, o);
        if (lane == 0)
            lg[s] = (mask[b * 200 + s] == 0) ? -1.0e9f : acc * 0.0625f;
    }
    __syncthreads();
    float v = (t < 200) ? lg[t] : -3.0e38f;
    float m = v;
    #pragma unroll
    for (int o = 16; o > 0; o >>= 1) m = fmaxf(m, __shfl_xor_sync(0xffffffffu, m, o));
    if (lane == 0) red[w] = m;
    __syncthreads();
    if (t == 0) {
        float mm = red[0];
        for (int i = 1; i < 8; i++) mm = fmaxf(mm, red[i]);
        red[0] = mm;
    }
    __syncthreads();
    float mx = red[0];
    float e = (t < 200) ? expf(v - mx) : 0.0f;
    __syncthreads();
    float ssum = e;
    #pragma unroll
    for (int o = 16; o > 0; o >>= 1) ssum += __shfl_xor_sync(0xffffffffu, ssum, o);
    if (lane == 0) red[w] = ssum;
    __syncthreads();
    if (t == 0) {
        float tt = 0.0f;
        for (int i = 0; i < 8; i++) tt += red[i];
        red[0] = tt;
    }
    __syncthreads();
    if (t < 200) g_att[b * 200 + t] = e / red[0];
}

// ---------------- K2: Gx GEMM via mma.sync bf16 (unchanged, proven 777us) -----
static constexpr int GX_TILE_BYTES = 16384;
static constexpr int GX_BUF_BYTES  = 2 * GX_TILE_BYTES;
static constexpr int GX_SMEM_BYTES = 1024 + 2 * GX_BUF_BYTES;

__global__ void __launch_bounds__(256, 1) gx_mma_kernel(const float* __restrict__ br,
                                                        const float* __restrict__ bu,
                                                        const float* __restrict__ bc)
{
    extern __shared__ char sm[];
    float* bias_s = (float*)sm;
    char* tiles = sm + 1024;
    uint32_t tiles_u = smem_u32(tiles);

    int t = threadIdx.x;
    int lane = t & 31, wid = t >> 5;
    int n0 = blockIdx.x * 128;
    int m0 = blockIdx.y * 128;

    if (t < 128) {
        int n = n0 + t;
        bias_s[t] = (n < 256) ? br[n] : (n < 512) ? bu[n - 256] : bc[n - 512];
    }

    int lrow = t >> 3;
    int lc16 = t & 7;
    const __nv_bfloat16* gA = g_abf + (size_t)(m0 + lrow) * KTOT + lc16 * 8;
    const __nv_bfloat16* gB = g_bbf + (size_t)(n0 + lrow) * KTOT + lc16 * 8;
    uint32_t sA[4], sB[4];
    #pragma unroll
    for (int r = 0; r < 4; r++) {
        uint32_t off = (uint32_t)((lrow + r * 32) * 128 + lc16 * 16);
        off ^= (off >> 3) & 0x70;
        sA[r] = tiles_u + off;
        sB[r] = tiles_u + GX_TILE_BYTES + off;
    }

    int wm = (wid >> 2) * 64;
    int wn = (wid & 3) * 32;
    uint32_t aR[4], aX[4], bR[2], bX[2];
    #pragma unroll
    for (int mf = 0; mf < 4; mf++) {
        uint32_t R = (uint32_t)(wm + mf * 16 + (lane & 15)) * 128;
        aR[mf] = R; aX[mf] = (R >> 3) & 0x70;
    }
    #pragma unroll
    for (int nf2 = 0; nf2 < 2; nf2++) {
        uint32_t R = (uint32_t)(wn + nf2 * 16 + (lane & 15)) * 128;
        bR[nf2] = R; bX[nf2] = (R >> 3) & 0x70;
    }
    uint32_t Ckl = ((uint32_t)(lane >> 4)) << 4;

    float d[4][4][4];
    #pragma unroll
    for (int i = 0; i < 4; i++)
        #pragma unroll
        for (int j = 0; j < 4; j++)
            #pragma unroll
            for (int r = 0; r < 4; r++) d[i][j][r] = 0.0f;

    #pragma unroll
    for (int r = 0; r < 4; r++) {
        CP_ASYNC16(sA[r], gA + (size_t)(r * 32) * KTOT);
        CP_ASYNC16(sB[r], gB + (size_t)(r * 32) * KTOT);
    }
    CP_COMMIT();

    const int NCHUNK = KTOT / 64;
    for (int c = 0; c < NCHUNK; c++) {
        int buf = c & 1;
        if (c + 1 < NCHUNK) {
            uint32_t bo = (uint32_t)((buf ^ 1) * GX_BUF_BYTES);
            int kc = (c + 1) * 64;
            #pragma unroll
            for (int r = 0; r < 4; r++) {
                CP_ASYNC16(sA[r] + bo, gA + (size_t)(r * 32) * KTOT + kc);
                CP_ASYNC16(sB[r] + bo, gB + (size_t)(r * 32) * KTOT + kc);
            }
            CP_COMMIT();
            CP_WAIT1();
        } else {
            CP_WAIT0();
        }
        __syncthreads();
        uint32_t abase = tiles_u + (uint32_t)(buf * GX_BUF_BYTES);
        uint32_t bbase = abase + GX_TILE_BYTES;
        #pragma unroll
        for (int ks = 0; ks < 4; ks++) {
            uint32_t C = (uint32_t)(ks * 32) + Ckl;
            uint32_t a[4][4], bb[2][4];
            #pragma unroll
            for (int mf = 0; mf < 4; mf++)
                LDSM4(a[mf], abase + aR[mf] + (C ^ aX[mf]));
            #pragma unroll
            for (int nf2 = 0; nf2 < 2; nf2++)
                LDSM4(bb[nf2], bbase + bR[nf2] + (C ^ bX[nf2]));
            #pragma unroll
            for (int mf = 0; mf < 4; mf++) {
                #pragma unroll
                for (int nf = 0; nf < 4; nf++) {
                    uint32_t b0 = bb[nf >> 1][nf & 1];
                    uint32_t b1 = bb[nf >> 1][(nf & 1) + 2];
                    MMA16816(d[mf][nf], a[mf], b0, b1);
                }
            }
        }
        __syncthreads();
    }

    int groupID = lane >> 2;
    int tc = (lane & 3) * 2;
    #pragma unroll
    for (int mf = 0; mf < 4; mf++) {
        #pragma unroll
        for (int half = 0; half < 2; half++) {
            int m = m0 + wm + mf * 16 + groupID + half * 8;
            int b = m / 200, s = m - b * 200;
            float* dst = g_gx + ((size_t)s * NB + b) * 768 + n0 + wn;
            #pragma unroll
            for (int nf = 0; nf < 4; nf++) {
                float2 bi = *(float2*)&bias_s[wn + nf * 8 + tc];
                float2 o = make_float2(d[mf][nf][half * 2 + 0] + bi.x,
                                       d[mf][nf][half * 2 + 1] + bi.y);
                *(float2*)(dst + nf * 8 + tc) = o;
            }
        }
    }
}

// ---------------- K3: GRU scan via mma.sync (32 CTAs x 32 rows) ---------------
// smem: A1 [0,49152) A2 [49152,98304) h [98304,131072) u' [131072,163840)
//       att[2][32] [163840,164096) mask[2][32] [164096,164352)
static constexpr int GRU_SMEM = 164352;

// K=768 fragment GEMM over 2 m16-tiles: acc[2][F][4] += A x B(frag layout)
template<int F>
__device__ __forceinline__ void gemm_frag2(uint32_t Abase, const char* pw,
                                           int lane, float acc[2][F][4])
{
    uint4 Bb[3][F];
    #pragma unroll
    for (int p = 0; p < 2; p++)
        #pragma unroll
        for (int f = 0; f < F; f++)
            Bb[p][f] = *(const uint4*)(pw + (f * 24 + p) * 512);
    #pragma unroll
    for (int t2 = 0; t2 < 24; t2++) {
        if (t2 < 22) {
            #pragma unroll
            for (int f = 0; f < F; f++)
                Bb[(t2 + 2) % 3][f] = *(const uint4*)(pw + (f * 24 + t2 + 2) * 512);
        }
        #pragma unroll
        for (int th = 0; th < 2; th++) {
            int seg = 4 * t2 + 2 * th + (lane >> 4);
            #pragma unroll
            for (int mt = 0; mt < 2; mt++) {
                int arow = mt * 16 + (lane & 15);
                uint32_t aaddr = Abase + (uint32_t)(arow * 1536)
                               + (uint32_t)(((seg & ~7) | ((seg ^ arow) & 7)) << 4);
                uint32_t a[4];
                LDSM4(a, aaddr);
                #pragma unroll
                for (int f = 0; f < F; f++) {
                    if (th == 0) MMA16816(acc[mt][f], a, Bb[t2 % 3][f].x, Bb[t2 % 3][f].y);
                    else         MMA16816(acc[mt][f], a, Bb[t2 % 3][f].z, Bb[t2 % 3][f].w);
                }
            }
        }
    }
}

__global__ void __launch_bounds__(256, 1) gru2_kernel(const int* __restrict__ mask,
                                                      const float* __restrict__ Wo,
                                                      const float* __restrict__ bo,
                                                      float* __restrict__ out)
{
    extern __shared__ char smx[];
    uint32_t a1u = smem_u32(smx);
    uint32_t a2u = a1u + 49152;
    float* h_sF = (float*)(smx + 98304);
    float* u_sF = (float*)(smx + 131072);
    float* a_sF = (float*)(smx + 163840);   // [2][32] parity-buffered
    int*   m_sI = (int*)(smx + 164096);     // [2][32] parity-buffered

    int b0 = blockIdx.x * 32;
    int t = threadIdx.x;
    int lane = t & 31, wid = t >> 5;
    int g = lane >> 2, tc = (lane & 3) * 2;

    const char* pw1 = (const char*)g_wruf + wid * 98304 + lane * 16;
    const char* pw2 = (const char*)g_wcf + wid * 49152 + lane * 16;

    // zero A1 (h=0 tile) + h
    #pragma unroll
    for (int i = 0; i < 48; i++) ((uint32_t*)smx)[t + i * 256] = 0u;
    #pragma unroll
    for (int i = 0; i < 32; i++) h_sF[t + i * 256] = 0.0f;
    if (t < 32) {
        a_sF[t] = g_att[(b0 + t) * NS];
        m_sI[t] = mask[(b0 + t) * NS];
    }
    float pool[2][4][4];
    #pragma unroll
    for (int mt = 0; mt < 2; mt++)
        #pragma unroll
        for (int f = 0; f < 4; f++)
            #pragma unroll
            for (int i = 0; i < 4; i++) pool[mt][f][i] = -3.0e38f;
    __syncthreads();

    #pragma unroll 1
    for (int s = 0; s < 200; s++) {
        int par = s & 1, nxt = par ^ 1;
        const float* gsrc = g_gx + ((size_t)s * NB + b0) * 768;

        // ---- GEMM1: preact_ru = gx + h @ Whru'^T
        float acc[2][8][4];
        #pragma unroll
        for (int mt = 0; mt < 2; mt++)
            #pragma unroll
            for (int f = 0; f < 8; f++) {
                int nidx = wid * 64 + f * 8 + tc;
                int r0 = mt * 16 + g;
                float2 v0 = *(const float2*)(gsrc + (size_t)r0 * 768 + nidx);
                float2 v1 = *(const float2*)(gsrc + (size_t)(r0 + 8) * 768 + nidx);
                acc[mt][f][0] = v0.x; acc[mt][f][1] = v0.y;
                acc[mt][f][2] = v1.x; acc[mt][f][3] = v1.y;
            }
        gemm_frag2<8>(a1u, pw1, lane, acc);

        // prefetch next-step att/mask into the OTHER parity buffer (race-free)
        if (t < 32 && s + 1 < 200) {
            a_sF[nxt * 32 + t] = g_att[(b0 + t) * NS + s + 1];
            m_sI[nxt * 32 + t] = mask[(b0 + t) * NS + s + 1];
        }

        // ---- gates: r -> rh into A2 ; u' = a*u into u_s
        if (wid < 4) {
            #pragma unroll
            for (int f = 0; f < 8; f++) {
                int j = wid * 64 + f * 8 + tc;
                #pragma unroll
                for (int mt = 0; mt < 2; mt++)
                    #pragma unroll
                    for (int half = 0; half < 2; half++) {
                        int m = mt * 16 + half * 8 + g;
                        float r0 = sig_(acc[mt][f][half * 2 + 0]);
                        float r1 = sig_(acc[mt][f][half * 2 + 1]);
                        float2 hh = *(float2*)(h_sF + m * 256 + j);
                        __nv_bfloat16 h0, l0, h1, l1;
                        bf16split(r0 * hh.x, h0, l0);
                        bf16split(r1 * hh.y, h1, l1);
                        uint32_t hp = (uint32_t)__bfloat16_as_ushort(h0) |
                                      ((uint32_t)__bfloat16_as_ushort(h1) << 16);
                        uint32_t lp = (uint32_t)__bfloat16_as_ushort(l0) |
                                      ((uint32_t)__bfloat16_as_ushort(l1) << 16);
                        *(uint32_t*)(smx + 49152 + a_off(m, j))       = hp;
                        *(uint32_t*)(smx + 49152 + a_off(m, 256 + j)) = hp;
                        *(uint32_t*)(smx + 49152 + a_off(m, 512 + j)) = lp;
                    }
            }
        } else {
            #pragma unroll
            for (int f = 0; f < 8; f++) {
                int j = (wid - 4) * 64 + f * 8 + tc;
                #pragma unroll
                for (int mt = 0; mt < 2; mt++)
                    #pragma unroll
                    for (int half = 0; half < 2; half++) {
                        int m = mt * 16 + half * 8 + g;
                        float am = a_sF[par * 32 + m];
                        float u0 = sig_(acc[mt][f][half * 2 + 0]) * am;
                        float u1 = sig_(acc[mt][f][half * 2 + 1]) * am;
                        *(float2*)(u_sF + m * 256 + j) = make_float2(u0, u1);
                    }
            }
        }
        __syncthreads();

        // ---- GEMM2: preact_c = gx_c + rh @ Whc'^T
        float acc2[2][4][4];
        #pragma unroll
        for (int mt = 0; mt < 2; mt++)
            #pragma unroll
            for (int f = 0; f < 4; f++) {
                int nidx = 512 + wid * 32 + f * 8 + tc;
                int r0 = mt * 16 + g;
                float2 v0 = *(const float2*)(gsrc + (size_t)r0 * 768 + nidx);
                float2 v1 = *(const float2*)(gsrc + (size_t)(r0 + 8) * 768 + nidx);
                acc2[mt][f][0] = v0.x; acc2[mt][f][1] = v0.y;
                acc2[mt][f][2] = v1.x; acc2[mt][f][3] = v1.y;
            }
        gemm_frag2<4>(a2u, pw2, lane, acc2);

        // ---- update: h += u'*(tanh(pre_c) - h); pool; write h fp32 + A1 bf16
        #pragma unroll
        for (int f = 0; f < 4; f++) {
            int j2 = wid * 32 + f * 8 + tc;
            #pragma unroll
            for (int mt = 0; mt < 2; mt++)
                #pragma unroll
                for (int half = 0; half < 2; half++) {
                    int m = mt * 16 + half * 8 + g;
                    float c0 = tanhf(acc2[mt][f][half * 2 + 0]);
                    float c1 = tanhf(acc2[mt][f][half * 2 + 1]);
                    float2 uu = *(float2*)(u_sF + m * 256 + j2);
                    float2 hh = *(float2*)(h_sF + m * 256 + j2);
                    float hn0 = hh.x + uu.x * (c0 - hh.x);
                    float hn1 = hh.y + uu.y * (c1 - hh.y);
                    *(float2*)(h_sF + m * 256 + j2) = make_float2(hn0, hn1);
                    int mk = m_sI[par * 32 + m];
                    pool[mt][f][half * 2 + 0] = fmaxf(pool[mt][f][half * 2 + 0], mk ? hn0 : 0.0f);
                    pool[mt][f][half * 2 + 1] = fmaxf(pool[mt][f][half * 2 + 1], mk ? hn1 : 0.0f);
                    __nv_bfloat16 h0, l0, h1, l1;
                    bf16split(hn0, h0, l0);
                    bf16split(hn1, h1, l1);
                    uint32_t hp = (uint32_t)__bfloat16_as_ushort(h0) |
                                  ((uint32_t)__bfloat16_as_ushort(h1) << 16);
                    uint32_t lp = (uint32_t)__bfloat16_as_ushort(l0) |
                                  ((uint32_t)__bfloat16_as_ushort(l1) << 16);
                    *(uint32_t*)(smx + a_off(m, j2))       = hp;
                    *(uint32_t*)(smx + a_off(m, 256 + j2)) = hp;
                    *(uint32_t*)(smx + a_off(m, 512 + j2)) = lp;
                }
        }
        __syncthreads();
    }

    // ---- epilogue: pooled -> u_s, then out = [h_last | pooled @ Wo^T + bo]
    #pragma unroll
    for (int f = 0; f < 4; f++) {
        int j2 = wid * 32 + f * 8 + tc;
        #pragma unroll
        for (int mt = 0; mt < 2; mt++)
            #pragma unroll
            for (int half = 0; half < 2; half++) {
                int m = mt * 16 + half * 8 + g;
                *(float2*)(u_sF + m * 256 + j2) =
                    make_float2(pool[mt][f][half * 2 + 0], pool[mt][f][half * 2 + 1]);
            }
    }
    __syncthreads();

    #pragma unroll
    for (int m = 0; m < 32; m++)
        out[(size_t)(b0 + m) * 512 + t] = h_sF[m * 256 + t];

    float wacc[32];
    #pragma unroll
    for (int m = 0; m < 32; m++) wacc[m] = 0.0f;
    #pragma unroll 4
    for (int k = 0; k < 256; k++) {
        float wv = Wo[t * 256 + k];
        #pragma unroll
        for (int m = 0; m < 32; m++) wacc[m] += u_sF[m * 256 + k] * wv;
    }
    float bb = bo[t];
    #pragma unroll
    for (int m = 0; m < 32; m++)
        out[(size_t)(b0 + m) * 512 + 256 + t] = wacc[m] + bb;
}

// ---------------- launch ------------------------------------------------------
extern "C" void kernel_launch(void* const* d_in, const int* in_sizes, int n_in,
                              void* d_out, int out_size)
{
    const float* hist = (const float*)d_in[0];
    const float* tgt  = (const float*)d_in[1];
    const int*   mask = (const int*)d_in[2];
    const float* Wr   = (const float*)d_in[3];
    const float* br   = (const float*)d_in[4];
    const float* Wu   = (const float*)d_in[5];
    const float* bu   = (const float*)d_in[6];
    const float* Wc   = (const float*)d_in[7];
    const float* bc   = (const float*)d_in[8];
    const float* Wo   = (const float*)d_in[9];
    const float* bo   = (const float*)d_in[10];
    float* out = (float*)d_out;

    cudaFuncSetAttribute(gx_mma_kernel, cudaFuncAttributeMaxDynamicSharedMemorySize,
                         GX_SMEM_BYTES);
    cudaFuncSetAttribute(gru2_kernel, cudaFuncAttributeMaxDynamicSharedMemorySize,
                         GRU_SMEM);

    prepw_kernel<<<3072, 256>>>(Wr, Wu, Wc);
    prepa_kernel<<<51200, 256>>>(hist);
    attn_kernel<<<NB, 256>>>(hist, tgt, mask);
    gx_mma_kernel<<<dim3(6, 1600), 256, GX_SMEM_BYTES>>>(br, bu, bc);
    gru2_kernel<<<32, 256, GRU_SMEM>>>(mask, Wo, bo, out);
}

// round 8
// speedup vs baseline: 1.9085x; 1.4545x over previous
#include <cuda_runtime.h>
#include <cuda_bf16.h>
#include <cstdint>
#include <math.h>

#define NB 1024
#define NS 200
#define NH 256
#define KTOT 768

// ---------------- scratch (device globals; no allocations allowed) ----------
static __device__ float g_att[NB * NS];                        // softmax attention [b][s]
static __device__ float g_gx[(size_t)NS * NB * 768];           // x-part preact [s][b][768]
static __device__ __nv_bfloat16 g_abf[(size_t)NB * NS * KTOT]; // A' = [Ah|Ah|Al] [m][768]
static __device__ __nv_bfloat16 g_bbf[768 * KTOT];             // B' = [Bh|Bl|Bh] [n][768]
static __device__ __nv_bfloat16 g_wruf[512 * 768];             // Whru' frag-layout (F=8)
static __device__ __nv_bfloat16 g_wcf[256 * 768];              // Whc'  frag-layout (F=4)

__device__ __forceinline__ float sig_(float x)  { return 1.0f / (1.0f + expf(-x)); }

__device__ __forceinline__ uint32_t smem_u32(const void* p) {
    uint32_t a;
    asm("{ .reg .u64 t; cvta.to.shared.u64 t, %1; cvt.u32.u64 %0, t; }" : "=r"(a) : "l"(p));
    return a;
}

#define CP_ASYNC16(dst, src) \
    asm volatile("cp.async.cg.shared.global [%0], [%1], 16;" :: "r"(dst), "l"(src))
#define CP_COMMIT() asm volatile("cp.async.commit_group;" ::: "memory")
#define CP_WAIT0()  asm volatile("cp.async.wait_group 0;" ::: "memory")
#define CP_WAIT1()  asm volatile("cp.async.wait_group 1;" ::: "memory")

#define LDSM4(r, addr)                                                            \
    asm volatile("ldmatrix.sync.aligned.m8n8.x4.shared.b16 {%0,%1,%2,%3}, [%4];"  \
                 : "=r"((r)[0]), "=r"((r)[1]), "=r"((r)[2]), "=r"((r)[3])         \
                 : "r"(addr))

#define MMA16816(d, a, b0, b1)                                                    \
    asm volatile("mma.sync.aligned.m16n8k16.row.col.f32.bf16.bf16.f32 "           \
                 "{%0,%1,%2,%3}, {%4,%5,%6,%7}, {%8,%9}, {%0,%1,%2,%3};"          \
                 : "+f"((d)[0]), "+f"((d)[1]), "+f"((d)[2]), "+f"((d)[3])         \
                 : "r"((a)[0]), "r"((a)[1]), "r"((a)[2]), "r"((a)[3]),            \
                   "r"(b0), "r"(b1))

// byte offset of weight element (n,k) in per-warp fragment layout (F frags/warp)
__device__ __forceinline__ uint32_t frag_off(int n, int k, int F, int slice_shift) {
    int w = n >> slice_shift;
    int f = (n >> 3) & (F - 1);
    int r = n & 7;
    int t2 = k >> 5;
    int th = (k >> 4) & 1;
    int kk = k & 15;
    int lane = (r << 2) | ((kk & 7) >> 1);
    int byte = (th << 3) | (((kk >> 3) & 1) << 2) | ((kk & 1) << 1);
    return (uint32_t)(((((w * F + f) * 24 + t2) * 32 + lane) << 4) + byte);
}

// swizzled byte offset within a 16x768-bf16 A-tile (1536B rows)
__device__ __forceinline__ uint32_t a_off(int m, int k) {
    int seg = k >> 3;
    int segs = (seg & ~7) | ((seg ^ m) & 7);
    return (uint32_t)(m * 1536 + segs * 16 + (k & 7) * 2);
}

__device__ __forceinline__ void bf16split(float x, __nv_bfloat16& h, __nv_bfloat16& l) {
    h = __float2bfloat16(x);
    l = __float2bfloat16(x - __bfloat162float(h));
}

// ---------------- K0a: weight packing ----------------------------------------
__global__ void prepw_kernel(const float* __restrict__ Wr, const float* __restrict__ Wu,
                             const float* __restrict__ Wc)
{
    int idx = blockIdx.x * blockDim.x + threadIdx.x;
    if (idx < 196608) {
        // gx B' = [Bh | Bl | Bh], [n][k] k-major (x-part cols 0..255)
        int n = idx >> 8, k = idx & 255;
        float v;
        if (n < 256)      v = Wr[n * 512 + k];
        else if (n < 512) v = Wu[(n - 256) * 512 + k];
        else              v = Wc[(n - 512) * 512 + k];
        __nv_bfloat16 hi, lo; bf16split(v, hi, lo);
        g_bbf[(size_t)n * KTOT + k]       = hi;
        g_bbf[(size_t)n * KTOT + 256 + k] = lo;
        g_bbf[(size_t)n * KTOT + 512 + k] = hi;
    } else if (idx < 196608 + 393216) {
        // Whru' fragment layout, K-concat [hi | lo | hi], h-part cols 256..511
        int e = idx - 196608;
        int n = e / 768, k = e - n * 768;
        int kk = k & 255;
        float v = (n < 256) ? Wr[n * 512 + 256 + kk] : Wu[(n - 256) * 512 + 256 + kk];
        __nv_bfloat16 hi, lo; bf16split(v, hi, lo);
        __nv_bfloat16 val = (k < 256) ? hi : (k < 512 ? lo : hi);
        *(__nv_bfloat16*)((char*)g_wruf + frag_off(n, k, 8, 6)) = val;
    } else if (idx < 196608 + 393216 + 196608) {
        int e = idx - 589824;
        int n = e / 768, k = e - n * 768;
        int kk = k & 255;
        float v = Wc[n * 512 + 256 + kk];
        __nv_bfloat16 hi, lo; bf16split(v, hi, lo);
        __nv_bfloat16 val = (k < 256) ? hi : (k < 512 ? lo : hi);
        *(__nv_bfloat16*)((char*)g_wcf + frag_off(n, k, 4, 5)) = val;
    }
}

// ---------------- K0b: hist -> A' = [Ah | Ah | Al] ----------------------------
__global__ void __launch_bounds__(256) prepa_kernel(const float* __restrict__ hist)
{
    size_t i = (size_t)blockIdx.x * 256 + threadIdx.x;
    int m = (int)(i >> 6);
    int kq = ((int)i & 63) * 4;
    float4 v = *(const float4*)(hist + (size_t)m * 256 + kq);
    float x[4] = {v.x, v.y, v.z, v.w};
    __nv_bfloat16 h[4], l[4];
    #pragma unroll
    for (int j = 0; j < 4; j++) bf16split(x[j], h[j], l[j]);
    uint32_t hi01 = (uint32_t)__bfloat16_as_ushort(h[0]) | ((uint32_t)__bfloat16_as_ushort(h[1]) << 16);
    uint32_t hi23 = (uint32_t)__bfloat16_as_ushort(h[2]) | ((uint32_t)__bfloat16_as_ushort(h[3]) << 16);
    uint32_t lo01 = (uint32_t)__bfloat16_as_ushort(l[0]) | ((uint32_t)__bfloat16_as_ushort(l[1]) << 16);
    uint32_t lo23 = (uint32_t)__bfloat16_as_ushort(l[2]) | ((uint32_t)__bfloat16_as_ushort(l[3]) << 16);
    __nv_bfloat16* row = g_abf + (size_t)m * KTOT + kq;
    *(uint2*)(row)       = make_uint2(hi01, hi23);
    *(uint2*)(row + 256) = make_uint2(hi01, hi23);
    *(uint2*)(row + 512) = make_uint2(lo01, lo23);
}

// ---------------- K1: attention softmax --------------------------------------
__global__ void __launch_bounds__(256) attn_kernel(const float* __restrict__ hist,
                                                   const float* __restrict__ tgt,
                                                   const int* __restrict__ mask)
{
    __shared__ float tg[256];
    __shared__ float lg[200];
    __shared__ float red[8];
    int b = blockIdx.x;
    int t = threadIdx.x;
    int lane = t & 31, w = t >> 5;
    tg[t] = tgt[b * 256 + t];
    __syncthreads();
    for (int s = w; s < 200; s += 8) {
        const float* hp = hist + ((size_t)(b * 200 + s)) * 256;
        float acc = 0.0f;
        #pragma unroll
        for (int i = 0; i < 8; i++) acc += hp[lane + 32 * i] * tg[lane + 32 * i];
        #pragma unroll
        for (int o = 16; o > 0; o >>= 1) acc += __shfl_xor_sync(0xffffffffu, acc, o);
        if (lane == 0)
            lg[s] = (mask[b * 200 + s] == 0) ? -1.0e9f : acc * 0.0625f;
    }
    __syncthreads();
    float v = (t < 200) ? lg[t] : -3.0e38f;
    float m = v;
    #pragma unroll
    for (int o = 16; o > 0; o >>= 1) m = fmaxf(m, __shfl_xor_sync(0xffffffffu, m, o));
    if (lane == 0) red[w] = m;
    __syncthreads();
    if (t == 0) {
        float mm = red[0];
        for (int i = 1; i < 8; i++) mm = fmaxf(mm, red[i]);
        red[0] = mm;
    }
    __syncthreads();
    float mx = red[0];
    float e = (t < 200) ? expf(v - mx) : 0.0f;
    __syncthreads();
    float ssum = e;
    #pragma unroll
    for (int o = 16; o > 0; o >>= 1) ssum += __shfl_xor_sync(0xffffffffu, ssum, o);
    if (lane == 0) red[w] = ssum;
    __syncthreads();
    if (t == 0) {
        float tt = 0.0f;
        for (int i = 0; i < 8; i++) tt += red[i];
        red[0] = tt;
    }
    __syncthreads();
    if (t < 200) g_att[b * 200 + t] = e / red[0];
}

// ---------------- K2: Gx GEMM via mma.sync bf16 (unchanged, proven) ----------
static constexpr int GX_TILE_BYTES = 16384;
static constexpr int GX_BUF_BYTES  = 2 * GX_TILE_BYTES;
static constexpr int GX_SMEM_BYTES = 1024 + 2 * GX_BUF_BYTES;

__global__ void __launch_bounds__(256, 1) gx_mma_kernel(const float* __restrict__ br,
                                                        const float* __restrict__ bu,
                                                        const float* __restrict__ bc)
{
    extern __shared__ char sm[];
    float* bias_s = (float*)sm;
    char* tiles = sm + 1024;
    uint32_t tiles_u = smem_u32(tiles);

    int t = threadIdx.x;
    int lane = t & 31, wid = t >> 5;
    int n0 = blockIdx.x * 128;
    int m0 = blockIdx.y * 128;

    if (t < 128) {
        int n = n0 + t;
        bias_s[t] = (n < 256) ? br[n] : (n < 512) ? bu[n - 256] : bc[n - 512];
    }

    int lrow = t >> 3;
    int lc16 = t & 7;
    const __nv_bfloat16* gA = g_abf + (size_t)(m0 + lrow) * KTOT + lc16 * 8;
    const __nv_bfloat16* gB = g_bbf + (size_t)(n0 + lrow) * KTOT + lc16 * 8;
    uint32_t sA[4], sB[4];
    #pragma unroll
    for (int r = 0; r < 4; r++) {
        uint32_t off = (uint32_t)((lrow + r * 32) * 128 + lc16 * 16);
        off ^= (off >> 3) & 0x70;
        sA[r] = tiles_u + off;
        sB[r] = tiles_u + GX_TILE_BYTES + off;
    }

    int wm = (wid >> 2) * 64;
    int wn = (wid & 3) * 32;
    uint32_t aR[4], aX[4], bR[2], bX[2];
    #pragma unroll
    for (int mf = 0; mf < 4; mf++) {
        uint32_t R = (uint32_t)(wm + mf * 16 + (lane & 15)) * 128;
        aR[mf] = R; aX[mf] = (R >> 3) & 0x70;
    }
    #pragma unroll
    for (int nf2 = 0; nf2 < 2; nf2++) {
        uint32_t R = (uint32_t)(wn + nf2 * 16 + (lane & 15)) * 128;
        bR[nf2] = R; bX[nf2] = (R >> 3) & 0x70;
    }
    uint32_t Ckl = ((uint32_t)(lane >> 4)) << 4;

    float d[4][4][4];
    #pragma unroll
    for (int i = 0; i < 4; i++)
        #pragma unroll
        for (int j = 0; j < 4; j++)
            #pragma unroll
            for (int r = 0; r < 4; r++) d[i][j][r] = 0.0f;

    #pragma unroll
    for (int r = 0; r < 4; r++) {
        CP_ASYNC16(sA[r], gA + (size_t)(r * 32) * KTOT);
        CP_ASYNC16(sB[r], gB + (size_t)(r * 32) * KTOT);
    }
    CP_COMMIT();

    const int NCHUNK = KTOT / 64;
    for (int c = 0; c < NCHUNK; c++) {
        int buf = c & 1;
        if (c + 1 < NCHUNK) {
            uint32_t bo = (uint32_t)((buf ^ 1) * GX_BUF_BYTES);
            int kc = (c + 1) * 64;
            #pragma unroll
            for (int r = 0; r < 4; r++) {
                CP_ASYNC16(sA[r] + bo, gA + (size_t)(r * 32) * KTOT + kc);
                CP_ASYNC16(sB[r] + bo, gB + (size_t)(r * 32) * KTOT + kc);
            }
            CP_COMMIT();
            CP_WAIT1();
        } else {
            CP_WAIT0();
        }
        __syncthreads();
        uint32_t abase = tiles_u + (uint32_t)(buf * GX_BUF_BYTES);
        uint32_t bbase = abase + GX_TILE_BYTES;
        #pragma unroll
        for (int ks = 0; ks < 4; ks++) {
            uint32_t C = (uint32_t)(ks * 32) + Ckl;
            uint32_t a[4][4], bb[2][4];
            #pragma unroll
            for (int mf = 0; mf < 4; mf++)
                LDSM4(a[mf], abase + aR[mf] + (C ^ aX[mf]));
            #pragma unroll
            for (int nf2 = 0; nf2 < 2; nf2++)
                LDSM4(bb[nf2], bbase + bR[nf2] + (C ^ bX[nf2]));
            #pragma unroll
            for (int mf = 0; mf < 4; mf++) {
                #pragma unroll
                for (int nf = 0; nf < 4; nf++) {
                    uint32_t b0 = bb[nf >> 1][nf & 1];
                    uint32_t b1 = bb[nf >> 1][(nf & 1) + 2];
                    MMA16816(d[mf][nf], a[mf], b0, b1);
                }
            }
        }
        __syncthreads();
    }

    int groupID = lane >> 2;
    int tc = (lane & 3) * 2;
    #pragma unroll
    for (int mf = 0; mf < 4; mf++) {
        #pragma unroll
        for (int half = 0; half < 2; half++) {
            int m = m0 + wm + mf * 16 + groupID + half * 8;
            int b = m / 200, s = m - b * 200;
            float* dst = g_gx + ((size_t)s * NB + b) * 768 + n0 + wn;
            #pragma unroll
            for (int nf = 0; nf < 4; nf++) {
                float2 bi = *(float2*)&bias_s[wn + nf * 8 + tc];
                float2 o = make_float2(d[mf][nf][half * 2 + 0] + bi.x,
                                       d[mf][nf][half * 2 + 1] + bi.y);
                *(float2*)(dst + nf * 8 + tc) = o;
            }
        }
    }
}

// ---------------- K3: GRU scan via mma.sync (64 CTAs x 16 rows) ---------------
// smem: A1 [0,24576) A2 [24576,49152) h [49152,65536) u' [65536,81920)
//       att[2][16] [81920,82048) mask[2][16] [82048,82176)
static constexpr int GRU_SMEM = 82176;

// One K=768 fragment GEMM: acc[F][4] += A(smem,swizzled) x B(global frag layout)
template<int F>
__device__ __forceinline__ void gemm_frag(uint32_t Abase, const char* pw,
                                          int lane, float acc[][4])
{
    uint4 Bb[3][F];
    #pragma unroll
    for (int p = 0; p < 2; p++)
        #pragma unroll
        for (int f = 0; f < F; f++)
            Bb[p][f] = *(const uint4*)(pw + (f * 24 + p) * 512);
    #pragma unroll
    for (int t2 = 0; t2 < 24; t2++) {
        if (t2 < 22) {
            #pragma unroll
            for (int f = 0; f < F; f++)
                Bb[(t2 + 2) % 3][f] = *(const uint4*)(pw + (f * 24 + t2 + 2) * 512);
        }
        #pragma unroll
        for (int th = 0; th < 2; th++) {
            int row = lane & 15;
            int seg = 4 * t2 + 2 * th + (lane >> 4);
            uint32_t aaddr = Abase + (uint32_t)(row * 1536)
                           + (uint32_t)(((seg & ~7) | ((seg ^ row) & 7)) << 4);
            uint32_t a[4];
            LDSM4(a, aaddr);
            #pragma unroll
            for (int f = 0; f < F; f++) {
                if (th == 0) MMA16816(acc[f], a, Bb[t2 % 3][f].x, Bb[t2 % 3][f].y);
                else         MMA16816(acc[f], a, Bb[t2 % 3][f].z, Bb[t2 % 3][f].w);
            }
        }
    }
}

__global__ void __launch_bounds__(256, 1) gru2_kernel(const int* __restrict__ mask,
                                                      const float* __restrict__ Wo,
                                                      const float* __restrict__ bo,
                                                      float* __restrict__ out)
{
    extern __shared__ char smx[];
    uint32_t a1u = smem_u32(smx);
    uint32_t a2u = a1u + 24576;
    float* h_sF = (float*)(smx + 49152);
    float* u_sF = (float*)(smx + 65536);
    float* a_sF = (float*)(smx + 81920);   // [2][16] parity-buffered
    int*   m_sI = (int*)(smx + 82048);     // [2][16] parity-buffered

    int b0 = blockIdx.x * 16;
    int t = threadIdx.x;
    int lane = t & 31, wid = t >> 5;
    int g = lane >> 2, tc = (lane & 3) * 2;

    const char* pw1 = (const char*)g_wruf + wid * 98304 + lane * 16;
    const char* pw2 = (const char*)g_wcf + wid * 49152 + lane * 16;

    // zero A1 (h=0 tile) + h
    #pragma unroll
    for (int i = 0; i < 24; i++) ((uint32_t*)smx)[t + i * 256] = 0u;
    #pragma unroll
    for (int i = 0; i < 16; i++) h_sF[t + i * 256] = 0.0f;
    if (t < 16) {
        a_sF[t] = g_att[(b0 + t) * NS];
        m_sI[t] = mask[(b0 + t) * NS];
    }
    float pool[4][4];
    #pragma unroll
    for (int f = 0; f < 4; f++)
        #pragma unroll
        for (int i = 0; i < 4; i++) pool[f][i] = -3.0e38f;
    __syncthreads();

    #pragma unroll 1
    for (int s = 0; s < 200; s++) {
        int par = s & 1, nxt = par ^ 1;
        const float* gsrc = g_gx + ((size_t)s * NB + b0) * 768;

        // ---- GEMM1: preact_ru = gx + h @ Whru'^T
        float acc[8][4];
        #pragma unroll
        for (int f = 0; f < 8; f++) {
            int nidx = wid * 64 + f * 8 + tc;
            float2 v0 = *(const float2*)(gsrc + (size_t)g * 768 + nidx);
            float2 v1 = *(const float2*)(gsrc + (size_t)(g + 8) * 768 + nidx);
            acc[f][0] = v0.x; acc[f][1] = v0.y; acc[f][2] = v1.x; acc[f][3] = v1.y;
        }
        gemm_frag<8>(a1u, pw1, lane, acc);

        // prefetch next-step att/mask into the OTHER parity buffer (race-free)
        if (t < 16 && s + 1 < 200) {
            a_sF[nxt * 16 + t] = g_att[(b0 + t) * NS + s + 1];
            m_sI[nxt * 16 + t] = mask[(b0 + t) * NS + s + 1];
        }

        // ---- gates: r -> rh into A2 ; u' = a*u into u_s
        if (wid < 4) {
            #pragma unroll
            for (int f = 0; f < 8; f++) {
                int j = wid * 64 + f * 8 + tc;
                #pragma unroll
                for (int half = 0; half < 2; half++) {
                    int m = half * 8 + g;
                    float r0 = sig_(acc[f][half * 2 + 0]);
                    float r1 = sig_(acc[f][half * 2 + 1]);
                    float2 hh = *(float2*)(h_sF + m * 256 + j);
                    __nv_bfloat16 h0, l0, h1, l1;
                    bf16split(r0 * hh.x, h0, l0);
                    bf16split(r1 * hh.y, h1, l1);
                    uint32_t hp = (uint32_t)__bfloat16_as_ushort(h0) |
                                  ((uint32_t)__bfloat16_as_ushort(h1) << 16);
                    uint32_t lp = (uint32_t)__bfloat16_as_ushort(l0) |
                                  ((uint32_t)__bfloat16_as_ushort(l1) << 16);
                    *(uint32_t*)(smx + 24576 + a_off(m, j))       = hp;
                    *(uint32_t*)(smx + 24576 + a_off(m, 256 + j)) = hp;
                    *(uint32_t*)(smx + 24576 + a_off(m, 512 + j)) = lp;
                }
            }
        } else {
            #pragma unroll
            for (int f = 0; f < 8; f++) {
                int j = (wid - 4) * 64 + f * 8 + tc;
                #pragma unroll
                for (int half = 0; half < 2; half++) {
                    int m = half * 8 + g;
                    float am = a_sF[par * 16 + m];
                    float u0 = sig_(acc[f][half * 2 + 0]) * am;
                    float u1 = sig_(acc[f][half * 2 + 1]) * am;
                    *(float2*)(u_sF + m * 256 + j) = make_float2(u0, u1);
                }
            }
        }
        __syncthreads();

        // ---- GEMM2: preact_c = gx_c + rh @ Whc'^T
        float acc2[4][4];
        #pragma unroll
        for (int f = 0; f < 4; f++) {
            int nidx = 512 + wid * 32 + f * 8 + tc;
            float2 v0 = *(const float2*)(gsrc + (size_t)g * 768 + nidx);
            float2 v1 = *(const float2*)(gsrc + (size_t)(g + 8) * 768 + nidx);
            acc2[f][0] = v0.x; acc2[f][1] = v0.y; acc2[f][2] = v1.x; acc2[f][3] = v1.y;
        }
        gemm_frag<4>(a2u, pw2, lane, acc2);

        // ---- update: h += u'*(tanh(pre_c) - h); pool; write h fp32 + A1 bf16
        #pragma unroll
        for (int f = 0; f < 4; f++) {
            int j2 = wid * 32 + f * 8 + tc;
            #pragma unroll
            for (int half = 0; half < 2; half++) {
                int m = half * 8 + g;
                float c0 = tanhf(acc2[f][half * 2 + 0]);
                float c1 = tanhf(acc2[f][half * 2 + 1]);
                float2 uu = *(float2*)(u_sF + m * 256 + j2);
                float2 hh = *(float2*)(h_sF + m * 256 + j2);
                float hn0 = hh.x + uu.x * (c0 - hh.x);
                float hn1 = hh.y + uu.y * (c1 - hh.y);
                *(float2*)(h_sF + m * 256 + j2) = make_float2(hn0, hn1);
                int mk = m_sI[par * 16 + m];
                pool[f][half * 2 + 0] = fmaxf(pool[f][half * 2 + 0], mk ? hn0 : 0.0f);
                pool[f][half * 2 + 1] = fmaxf(pool[f][half * 2 + 1], mk ? hn1 : 0.0f);
                __nv_bfloat16 h0, l0, h1, l1;
                bf16split(hn0, h0, l0);
                bf16split(hn1, h1, l1);
                uint32_t hp = (uint32_t)__bfloat16_as_ushort(h0) |
                              ((uint32_t)__bfloat16_as_ushort(h1) << 16);
                uint32_t lp = (uint32_t)__bfloat16_as_ushort(l0) |
                              ((uint32_t)__bfloat16_as_ushort(l1) << 16);
                *(uint32_t*)(smx + a_off(m, j2))       = hp;
                *(uint32_t*)(smx + a_off(m, 256 + j2)) = hp;
                *(uint32_t*)(smx + a_off(m, 512 + j2)) = lp;
            }
        }
        __syncthreads();
    }

    // ---- epilogue: pooled -> u_s, then out = [h_last | pooled @ Wo^T + bo]
    #pragma unroll
    for (int f = 0; f < 4; f++) {
        int j2 = wid * 32 + f * 8 + tc;
        #pragma unroll
        for (int half = 0; half < 2; half++) {
            int m = half * 8 + g;
            *(float2*)(u_sF + m * 256 + j2) =
                make_float2(pool[f][half * 2 + 0], pool[f][half * 2 + 1]);
        }
    }
    __syncthreads();

    #pragma unroll
    for (int m = 0; m < 16; m++)
        out[(size_t)(b0 + m) * 512 + t] = h_sF[m * 256 + t];

    float wacc[16];
    #pragma unroll
    for (int m = 0; m < 16; m++) wacc[m] = 0.0f;
    #pragma unroll 4
    for (int k = 0; k < 256; k++) {
        float wv = Wo[t * 256 + k];
        #pragma unroll
        for (int m = 0; m < 16; m++) wacc[m] += u_sF[m * 256 + k] * wv;
    }
    float bb = bo[t];
    #pragma unroll
    for (int m = 0; m < 16; m++)
        out[(size_t)(b0 + m) * 512 + 256 + t] = wacc[m] + bb;
}

// ---------------- launch ------------------------------------------------------
extern "C" void kernel_launch(void* const* d_in, const int* in_sizes, int n_in,
                              void* d_out, int out_size)
{
    const float* hist = (const float*)d_in[0];
    const float* tgt  = (const float*)d_in[1];
    const int*   mask = (const int*)d_in[2];
    const float* Wr   = (const float*)d_in[3];
    const float* br   = (const float*)d_in[4];
    const float* Wu   = (const float*)d_in[5];
    const float* bu   = (const float*)d_in[6];
    const float* Wc   = (const float*)d_in[7];
    const float* bc   = (const float*)d_in[8];
    const float* Wo   = (const float*)d_in[9];
    const float* bo   = (const float*)d_in[10];
    float* out = (float*)d_out;

    cudaFuncSetAttribute(gx_mma_kernel, cudaFuncAttributeMaxDynamicSharedMemorySize,
                         GX_SMEM_BYTES);
    cudaFuncSetAttribute(gru2_kernel, cudaFuncAttributeMaxDynamicSharedMemorySize,
                         GRU_SMEM);

    prepw_kernel<<<3072, 256>>>(Wr, Wu, Wc);
    prepa_kernel<<<51200, 256>>>(hist);
    attn_kernel<<<NB, 256>>>(hist, tgt, mask);
    gx_mma_kernel<<<dim3(6, 1600), 256, GX_SMEM_BYTES>>>(br, bu, bc);
    gru2_kernel<<<64, 256, GRU_SMEM>>>(mask, Wo, bo, out);
}

// round 9
// speedup vs baseline: 2.2777x; 1.1934x over previous
#include <cuda_runtime.h>
#include <cuda_bf16.h>
#include <cstdint>
#include <math.h>

#define NB 1024
#define NS 200
#define NH 256
#define KTOT 768

// ---------------- scratch (device globals; no allocations allowed) ----------
static __device__ float g_att[NB * NS];                        // softmax attention [b][s]
static __device__ float g_gx[(size_t)NS * NB * 768];           // x-part preact [s][b][768]
static __device__ __nv_bfloat16 g_abf[(size_t)NB * NS * KTOT]; // A' = [Ah|Ah|Al] [m][768] (gx)
static __device__ __nv_bfloat16 g_bbf[768 * KTOT];             // B' = [Bh|Bl|Bh] [n][768] (gx)
static __device__ __nv_bfloat16 g_wruf[512 * 512];             // Whru' frag-layout K=512 (F=8)
static __device__ __nv_bfloat16 g_wcf[256 * 512];              // Whc'  frag-layout K=512 (F=4)

__device__ __forceinline__ float sig_(float x)  { return 1.0f / (1.0f + expf(-x)); }

__device__ __forceinline__ uint32_t smem_u32(const void* p) {
    uint32_t a;
    asm("{ .reg .u64 t; cvta.to.shared.u64 t, %1; cvt.u32.u64 %0, t; }" : "=r"(a) : "l"(p));
    return a;
}

#define CP_ASYNC16(dst, src) \
    asm volatile("cp.async.cg.shared.global [%0], [%1], 16;" :: "r"(dst), "l"(src))
#define CP_COMMIT() asm volatile("cp.async.commit_group;" ::: "memory")
#define CP_WAIT0()  asm volatile("cp.async.wait_group 0;" ::: "memory")
#define CP_WAIT1()  asm volatile("cp.async.wait_group 1;" ::: "memory")

#define LDSM4(r, addr)                                                            \
    asm volatile("ldmatrix.sync.aligned.m8n8.x4.shared.b16 {%0,%1,%2,%3}, [%4];"  \
                 : "=r"((r)[0]), "=r"((r)[1]), "=r"((r)[2]), "=r"((r)[3])         \
                 : "r"(addr))

#define MMA16816(d, a, b0, b1)                                                    \
    asm volatile("mma.sync.aligned.m16n8k16.row.col.f32.bf16.bf16.f32 "           \
                 "{%0,%1,%2,%3}, {%4,%5,%6,%7}, {%8,%9}, {%0,%1,%2,%3};"          \
                 : "+f"((d)[0]), "+f"((d)[1]), "+f"((d)[2]), "+f"((d)[3])         \
                 : "r"((a)[0]), "r"((a)[1]), "r"((a)[2]), "r"((a)[3]),            \
                   "r"(b0), "r"(b1))

// byte offset of weight element (n,k) in per-warp fragment layout
// F = frags/warp, sshift = log2(n-cols per warp), NT2 = K/32 chunks
__device__ __forceinline__ uint32_t frag_off(int n, int k, int F, int sshift, int NT2) {
    int w = n >> sshift;
    int f = (n >> 3) & (F - 1);
    int r = n & 7;
    int t2 = k >> 5;
    int th = (k >> 4) & 1;
    int kk = k & 15;
    int lane = (r << 2) | ((kk & 7) >> 1);
    int byte = (th << 3) | (((kk >> 3) & 1) << 2) | ((kk & 1) << 1);
    return (uint32_t)(((((w * F + f) * NT2 + t2) * 32 + lane) << 4) + byte);
}

// swizzled byte offset within a 16x512-bf16 A-tile (1024B rows)
__device__ __forceinline__ uint32_t a_off(int m, int k) {
    int seg = k >> 3;
    int segs = (seg & ~7) | ((seg ^ m) & 7);
    return (uint32_t)(m * 1024 + segs * 16 + (k & 7) * 2);
}

__device__ __forceinline__ void bf16split(float x, __nv_bfloat16& h, __nv_bfloat16& l) {
    h = __float2bfloat16(x);
    l = __float2bfloat16(x - __bfloat162float(h));
}

// ---------------- K0a: weight packing ----------------------------------------
__global__ void prepw_kernel(const float* __restrict__ Wr, const float* __restrict__ Wu,
                             const float* __restrict__ Wc)
{
    int idx = blockIdx.x * blockDim.x + threadIdx.x;
    if (idx < 196608) {
        // gx B' = [Bh | Bl | Bh], [n][k] k-major (x-part cols 0..255) -- 3-term
        int n = idx >> 8, k = idx & 255;
        float v;
        if (n < 256)      v = Wr[n * 512 + k];
        else if (n < 512) v = Wu[(n - 256) * 512 + k];
        else              v = Wc[(n - 512) * 512 + k];
        __nv_bfloat16 hi, lo; bf16split(v, hi, lo);
        g_bbf[(size_t)n * KTOT + k]       = hi;
        g_bbf[(size_t)n * KTOT + 256 + k] = lo;
        g_bbf[(size_t)n * KTOT + 512 + k] = hi;
    } else if (idx < 196608 + 262144) {
        // Whru' frag layout, K-concat [hi | lo] (K=512), h-part cols 256..511
        int e = idx - 196608;
        int n = e >> 9, k = e & 511;
        int kk = k & 255;
        float v = (n < 256) ? Wr[n * 512 + 256 + kk] : Wu[(n - 256) * 512 + 256 + kk];
        __nv_bfloat16 hi, lo; bf16split(v, hi, lo);
        __nv_bfloat16 val = (k < 256) ? hi : lo;
        *(__nv_bfloat16*)((char*)g_wruf + frag_off(n, k, 8, 6, 16)) = val;
    } else if (idx < 196608 + 262144 + 131072) {
        int e = idx - (196608 + 262144);
        int n = e >> 9, k = e & 511;
        int kk = k & 255;
        float v = Wc[n * 512 + 256 + kk];
        __nv_bfloat16 hi, lo; bf16split(v, hi, lo);
        __nv_bfloat16 val = (k < 256) ? hi : lo;
        *(__nv_bfloat16*)((char*)g_wcf + frag_off(n, k, 4, 5, 16)) = val;
    }
}

// ---------------- K0b: hist -> A' = [Ah | Ah | Al] (gx, 3-term) ---------------
__global__ void __launch_bounds__(256) prepa_kernel(const float* __restrict__ hist)
{
    size_t i = (size_t)blockIdx.x * 256 + threadIdx.x;
    int m = (int)(i >> 6);
    int kq = ((int)i & 63) * 4;
    float4 v = *(const float4*)(hist + (size_t)m * 256 + kq);
    float x[4] = {v.x, v.y, v.z, v.w};
    __nv_bfloat16 h[4], l[4];
    #pragma unroll
    for (int j = 0; j < 4; j++) bf16split(x[j], h[j], l[j]);
    uint32_t hi01 = (uint32_t)__bfloat16_as_ushort(h[0]) | ((uint32_t)__bfloat16_as_ushort(h[1]) << 16);
    uint32_t hi23 = (uint32_t)__bfloat16_as_ushort(h[2]) | ((uint32_t)__bfloat16_as_ushort(h[3]) << 16);
    uint32_t lo01 = (uint32_t)__bfloat16_as_ushort(l[0]) | ((uint32_t)__bfloat16_as_ushort(l[1]) << 16);
    uint32_t lo23 = (uint32_t)__bfloat16_as_ushort(l[2]) | ((uint32_t)__bfloat16_as_ushort(l[3]) << 16);
    __nv_bfloat16* row = g_abf + (size_t)m * KTOT + kq;
    *(uint2*)(row)       = make_uint2(hi01, hi23);
    *(uint2*)(row + 256) = make_uint2(hi01, hi23);
    *(uint2*)(row + 512) = make_uint2(lo01, lo23);
}

// ---------------- K1: attention softmax --------------------------------------
__global__ void __launch_bounds__(256) attn_kernel(const float* __restrict__ hist,
                                                   const float* __restrict__ tgt,
                                                   const int* __restrict__ mask)
{
    __shared__ float tg[256];
    __shared__ float lg[200];
    __shared__ float red[8];
    int b = blockIdx.x;
    int t = threadIdx.x;
    int lane = t & 31, w = t >> 5;
    tg[t] = tgt[b * 256 + t];
    __syncthreads();
    for (int s = w; s < 200; s += 8) {
        const float* hp = hist + ((size_t)(b * 200 + s)) * 256;
        float acc = 0.0f;
        #pragma unroll
        for (int i = 0; i < 8; i++) acc += hp[lane + 32 * i] * tg[lane + 32 * i];
        #pragma unroll
        for (int o = 16; o > 0; o >>= 1) acc += __shfl_xor_sync(0xffffffffu, acc, o);
        if (lane == 0)
            lg[s] = (mask[b * 200 + s] == 0) ? -1.0e9f : acc * 0.0625f;
    }
    __syncthreads();
    float v = (t < 200) ? lg[t] : -3.0e38f;
    float m = v;
    #pragma unroll
    for (int o = 16; o > 0; o >>= 1) m = fmaxf(m, __shfl_xor_sync(0xffffffffu, m, o));
    if (lane == 0) red[w] = m;
    __syncthreads();
    if (t == 0) {
        float mm = red[0];
        for (int i = 1; i < 8; i++) mm = fmaxf(mm, red[i]);
        red[0] = mm;
    }
    __syncthreads();
    float mx = red[0];
    float e = (t < 200) ? expf(v - mx) : 0.0f;
    __syncthreads();
    float ssum = e;
    #pragma unroll
    for (int o = 16; o > 0; o >>= 1) ssum += __shfl_xor_sync(0xffffffffu, ssum, o);
    if (lane == 0) red[w] = ssum;
    __syncthreads();
    if (t == 0) {
        float tt = 0.0f;
        for (int i = 0; i < 8; i++) tt += red[i];
        red[0] = tt;
    }
    __syncthreads();
    if (t < 200) g_att[b * 200 + t] = e / red[0];
}

// ---------------- K2: Gx GEMM via mma.sync bf16 (unchanged, proven) ----------
static constexpr int GX_TILE_BYTES = 16384;
static constexpr int GX_BUF_BYTES  = 2 * GX_TILE_BYTES;
static constexpr int GX_SMEM_BYTES = 1024 + 2 * GX_BUF_BYTES;

__global__ void __launch_bounds__(256, 1) gx_mma_kernel(const float* __restrict__ br,
                                                        const float* __restrict__ bu,
                                                        const float* __restrict__ bc)
{
    extern __shared__ char sm[];
    float* bias_s = (float*)sm;
    char* tiles = sm + 1024;
    uint32_t tiles_u = smem_u32(tiles);

    int t = threadIdx.x;
    int lane = t & 31, wid = t >> 5;
    int n0 = blockIdx.x * 128;
    int m0 = blockIdx.y * 128;

    if (t < 128) {
        int n = n0 + t;
        bias_s[t] = (n < 256) ? br[n] : (n < 512) ? bu[n - 256] : bc[n - 512];
    }

    int lrow = t >> 3;
    int lc16 = t & 7;
    const __nv_bfloat16* gA = g_abf + (size_t)(m0 + lrow) * KTOT + lc16 * 8;
    const __nv_bfloat16* gB = g_bbf + (size_t)(n0 + lrow) * KTOT + lc16 * 8;
    uint32_t sA[4], sB[4];
    #pragma unroll
    for (int r = 0; r < 4; r++) {
        uint32_t off = (uint32_t)((lrow + r * 32) * 128 + lc16 * 16);
        off ^= (off >> 3) & 0x70;
        sA[r] = tiles_u + off;
        sB[r] = tiles_u + GX_TILE_BYTES + off;
    }

    int wm = (wid >> 2) * 64;
    int wn = (wid & 3) * 32;
    uint32_t aR[4], aX[4], bR[2], bX[2];
    #pragma unroll
    for (int mf = 0; mf < 4; mf++) {
        uint32_t R = (uint32_t)(wm + mf * 16 + (lane & 15)) * 128;
        aR[mf] = R; aX[mf] = (R >> 3) & 0x70;
    }
    #pragma unroll
    for (int nf2 = 0; nf2 < 2; nf2++) {
        uint32_t R = (uint32_t)(wn + nf2 * 16 + (lane & 15)) * 128;
        bR[nf2] = R; bX[nf2] = (R >> 3) & 0x70;
    }
    uint32_t Ckl = ((uint32_t)(lane >> 4)) << 4;

    float d[4][4][4];
    #pragma unroll
    for (int i = 0; i < 4; i++)
        #pragma unroll
        for (int j = 0; j < 4; j++)
            #pragma unroll
            for (int r = 0; r < 4; r++) d[i][j][r] = 0.0f;

    #pragma unroll
    for (int r = 0; r < 4; r++) {
        CP_ASYNC16(sA[r], gA + (size_t)(r * 32) * KTOT);
        CP_ASYNC16(sB[r], gB + (size_t)(r * 32) * KTOT);
    }
    CP_COMMIT();

    const int NCHUNK = KTOT / 64;
    for (int c = 0; c < NCHUNK; c++) {
        int buf = c & 1;
        if (c + 1 < NCHUNK) {
            uint32_t bo = (uint32_t)((buf ^ 1) * GX_BUF_BYTES);
            int kc = (c + 1) * 64;
            #pragma unroll
            for (int r = 0; r < 4; r++) {
                CP_ASYNC16(sA[r] + bo, gA + (size_t)(r * 32) * KTOT + kc);
                CP_ASYNC16(sB[r] + bo, gB + (size_t)(r * 32) * KTOT + kc);
            }
            CP_COMMIT();
            CP_WAIT1();
        } else {
            CP_WAIT0();
        }
        __syncthreads();
        uint32_t abase = tiles_u + (uint32_t)(buf * GX_BUF_BYTES);
        uint32_t bbase = abase + GX_TILE_BYTES;
        #pragma unroll
        for (int ks = 0; ks < 4; ks++) {
            uint32_t C = (uint32_t)(ks * 32) + Ckl;
            uint32_t a[4][4], bb[2][4];
            #pragma unroll
            for (int mf = 0; mf < 4; mf++)
                LDSM4(a[mf], abase + aR[mf] + (C ^ aX[mf]));
            #pragma unroll
            for (int nf2 = 0; nf2 < 2; nf2++)
                LDSM4(bb[nf2], bbase + bR[nf2] + (C ^ bX[nf2]));
            #pragma unroll
            for (int mf = 0; mf < 4; mf++) {
                #pragma unroll
                for (int nf = 0; nf < 4; nf++) {
                    uint32_t b0 = bb[nf >> 1][nf & 1];
                    uint32_t b1 = bb[nf >> 1][(nf & 1) + 2];
                    MMA16816(d[mf][nf], a[mf], b0, b1);
                }
            }
        }
        __syncthreads();
    }

    int groupID = lane >> 2;
    int tc = (lane & 3) * 2;
    #pragma unroll
    for (int mf = 0; mf < 4; mf++) {
        #pragma unroll
        for (int half = 0; half < 2; half++) {
            int m = m0 + wm + mf * 16 + groupID + half * 8;
            int b = m / 200, s = m - b * 200;
            float* dst = g_gx + ((size_t)s * NB + b) * 768 + n0 + wn;
            #pragma unroll
            for (int nf = 0; nf < 4; nf++) {
                float2 bi = *(float2*)&bias_s[wn + nf * 8 + tc];
                float2 o = make_float2(d[mf][nf][half * 2 + 0] + bi.x,
                                       d[mf][nf][half * 2 + 1] + bi.y);
                *(float2*)(dst + nf * 8 + tc) = o;
            }
        }
    }
}

// ---------------- K3: GRU scan via mma.sync (64 CTAs x 16 rows, K=512) --------
// smem: A1 [0,16384) A2 [16384,32768) h [32768,49152) u' [49152,65536)
//       att[2][16] [65536,65664) mask[2][16] [65664,65792)
static constexpr int GRU_SMEM = 65792;

// K=512 fragment GEMM: acc[F][4] += A(smem,swizzled) x B(global frag layout)
template<int F>
__device__ __forceinline__ void gemm_frag(uint32_t Abase, const char* pw,
                                          int lane, float acc[][4])
{
    uint4 Bb[3][F];
    #pragma unroll
    for (int p = 0; p < 2; p++)
        #pragma unroll
        for (int f = 0; f < F; f++)
            Bb[p][f] = *(const uint4*)(pw + (f * 16 + p) * 512);
    #pragma unroll
    for (int t2 = 0; t2 < 16; t2++) {
        if (t2 < 14) {
            #pragma unroll
            for (int f = 0; f < F; f++)
                Bb[(t2 + 2) % 3][f] = *(const uint4*)(pw + (f * 16 + t2 + 2) * 512);
        }
        #pragma unroll
        for (int th = 0; th < 2; th++) {
            int row = lane & 15;
            int seg = 4 * t2 + 2 * th + (lane >> 4);
            uint32_t aaddr = Abase + (uint32_t)(row * 1024)
                           + (uint32_t)(((seg & ~7) | ((seg ^ row) & 7)) << 4);
            uint32_t a[4];
            LDSM4(a, aaddr);
            #pragma unroll
            for (int f = 0; f < F; f++) {
                if (th == 0) MMA16816(acc[f], a, Bb[t2 % 3][f].x, Bb[t2 % 3][f].y);
                else         MMA16816(acc[f], a, Bb[t2 % 3][f].z, Bb[t2 % 3][f].w);
            }
        }
    }
}

__global__ void __launch_bounds__(256, 1) gru2_kernel(const int* __restrict__ mask,
                                                      const float* __restrict__ Wo,
                                                      const float* __restrict__ bo,
                                                      float* __restrict__ out)
{
    extern __shared__ char smx[];
    uint32_t a1u = smem_u32(smx);
    uint32_t a2u = a1u + 16384;
    float* h_sF = (float*)(smx + 32768);
    float* u_sF = (float*)(smx + 49152);
    float* a_sF = (float*)(smx + 65536);   // [2][16] parity-buffered
    int*   m_sI = (int*)(smx + 65664);     // [2][16] parity-buffered

    int b0 = blockIdx.x * 16;
    int t = threadIdx.x;
    int lane = t & 31, wid = t >> 5;
    int g = lane >> 2, tc = (lane & 3) * 2;

    const char* pw1 = (const char*)g_wruf + wid * 65536 + lane * 16;
    const char* pw2 = (const char*)g_wcf + wid * 32768 + lane * 16;

    // zero A1 (h=0 tile) + h
    #pragma unroll
    for (int i = 0; i < 16; i++) ((uint32_t*)smx)[t + i * 256] = 0u;
    #pragma unroll
    for (int i = 0; i < 16; i++) h_sF[t + i * 256] = 0.0f;
    if (t < 16) {
        a_sF[t] = g_att[(b0 + t) * NS];
        m_sI[t] = mask[(b0 + t) * NS];
    }
    float pool[4][4];
    #pragma unroll
    for (int f = 0; f < 4; f++)
        #pragma unroll
        for (int i = 0; i < 4; i++) pool[f][i] = -3.0e38f;
    __syncthreads();

    #pragma unroll 1
    for (int s = 0; s < 200; s++) {
        int par = s & 1, nxt = par ^ 1;
        const float* gsrc = g_gx + ((size_t)s * NB + b0) * 768;

        // ---- GEMM1: preact_ru = gx + h @ Whru'^T
        float acc[8][4];
        #pragma unroll
        for (int f = 0; f < 8; f++) {
            int nidx = wid * 64 + f * 8 + tc;
            float2 v0 = *(const float2*)(gsrc + (size_t)g * 768 + nidx);
            float2 v1 = *(const float2*)(gsrc + (size_t)(g + 8) * 768 + nidx);
            acc[f][0] = v0.x; acc[f][1] = v0.y; acc[f][2] = v1.x; acc[f][3] = v1.y;
        }
        gemm_frag<8>(a1u, pw1, lane, acc);

        // prefetch next-step att/mask into the OTHER parity buffer (race-free)
        if (t < 16 && s + 1 < 200) {
            a_sF[nxt * 16 + t] = g_att[(b0 + t) * NS + s + 1];
            m_sI[nxt * 16 + t] = mask[(b0 + t) * NS + s + 1];
        }

        // ---- gates: r -> rh into A2 ; u' = a*u into u_s
        if (wid < 4) {
            #pragma unroll
            for (int f = 0; f < 8; f++) {
                int j = wid * 64 + f * 8 + tc;
                #pragma unroll
                for (int half = 0; half < 2; half++) {
                    int m = half * 8 + g;
                    float r0 = sig_(acc[f][half * 2 + 0]);
                    float r1 = sig_(acc[f][half * 2 + 1]);
                    float2 hh = *(float2*)(h_sF + m * 256 + j);
                    __nv_bfloat16 h0 = __float2bfloat16(r0 * hh.x);
                    __nv_bfloat16 h1 = __float2bfloat16(r1 * hh.y);
                    uint32_t hp = (uint32_t)__bfloat16_as_ushort(h0) |
                                  ((uint32_t)__bfloat16_as_ushort(h1) << 16);
                    *(uint32_t*)(smx + 16384 + a_off(m, j))       = hp;
                    *(uint32_t*)(smx + 16384 + a_off(m, 256 + j)) = hp;
                }
            }
        } else {
            #pragma unroll
            for (int f = 0; f < 8; f++) {
                int j = (wid - 4) * 64 + f * 8 + tc;
                #pragma unroll
                for (int half = 0; half < 2; half++) {
                    int m = half * 8 + g;
                    float am = a_sF[par * 16 + m];
                    float u0 = sig_(acc[f][half * 2 + 0]) * am;
                    float u1 = sig_(acc[f][half * 2 + 1]) * am;
                    *(float2*)(u_sF + m * 256 + j) = make_float2(u0, u1);
                }
            }
        }
        __syncthreads();

        // ---- GEMM2: preact_c = gx_c + rh @ Whc'^T
        float acc2[4][4];
        #pragma unroll
        for (int f = 0; f < 4; f++) {
            int nidx = 512 + wid * 32 + f * 8 + tc;
            float2 v0 = *(const float2*)(gsrc + (size_t)g * 768 + nidx);
            float2 v1 = *(const float2*)(gsrc + (size_t)(g + 8) * 768 + nidx);
            acc2[f][0] = v0.x; acc2[f][1] = v0.y; acc2[f][2] = v1.x; acc2[f][3] = v1.y;
        }
        gemm_frag<4>(a2u, pw2, lane, acc2);

        // ---- update: h += u'*(tanh(pre_c) - h); pool; write h fp32 + A1 bf16
        #pragma unroll
        for (int f = 0; f < 4; f++) {
            int j2 = wid * 32 + f * 8 + tc;
            #pragma unroll
            for (int half = 0; half < 2; half++) {
                int m = half * 8 + g;
                float c0 = tanhf(acc2[f][half * 2 + 0]);
                float c1 = tanhf(acc2[f][half * 2 + 1]);
                float2 uu = *(float2*)(u_sF + m * 256 + j2);
                float2 hh = *(float2*)(h_sF + m * 256 + j2);
                float hn0 = hh.x + uu.x * (c0 - hh.x);
                float hn1 = hh.y + uu.y * (c1 - hh.y);
                *(float2*)(h_sF + m * 256 + j2) = make_float2(hn0, hn1);
                int mk = m_sI[par * 16 + m];
                pool[f][half * 2 + 0] = fmaxf(pool[f][half * 2 + 0], mk ? hn0 : 0.0f);
                pool[f][half * 2 + 1] = fmaxf(pool[f][half * 2 + 1], mk ? hn1 : 0.0f);
                __nv_bfloat16 h0 = __float2bfloat16(hn0);
                __nv_bfloat16 h1 = __float2bfloat16(hn1);
                uint32_t hp = (uint32_t)__bfloat16_as_ushort(h0) |
                              ((uint32_t)__bfloat16_as_ushort(h1) << 16);
                *(uint32_t*)(smx + a_off(m, j2))       = hp;
                *(uint32_t*)(smx + a_off(m, 256 + j2)) = hp;
            }
        }
        __syncthreads();
    }

    // ---- epilogue: pooled -> u_s, then out = [h_last | pooled @ Wo^T + bo]
    #pragma unroll
    for (int f = 0; f < 4; f++) {
        int j2 = wid * 32 + f * 8 + tc;
        #pragma unroll
        for (int half = 0; half < 2; half++) {
            int m = half * 8 + g;
            *(float2*)(u_sF + m * 256 + j2) =
                make_float2(pool[f][half * 2 + 0], pool[f][half * 2 + 1]);
        }
    }
    __syncthreads();

    #pragma unroll
    for (int m = 0; m < 16; m++)
        out[(size_t)(b0 + m) * 512 + t] = h_sF[m * 256 + t];

    float wacc[16];
    #pragma unroll
    for (int m = 0; m < 16; m++) wacc[m] = 0.0f;
    #pragma unroll 4
    for (int k = 0; k < 256; k++) {
        float wv = Wo[t * 256 + k];
        #pragma unroll
        for (int m = 0; m < 16; m++) wacc[m] += u_sF[m * 256 + k] * wv;
    }
    float bb = bo[t];
    #pragma unroll
    for (int m = 0; m < 16; m++)
        out[(size_t)(b0 + m) * 512 + 256 + t] = wacc[m] + bb;
}

// ---------------- launch ------------------------------------------------------
extern "C" void kernel_launch(void* const* d_in, const int* in_sizes, int n_in,
                              void* d_out, int out_size)
{
    const float* hist = (const float*)d_in[0];
    const float* tgt  = (const float*)d_in[1];
    const int*   mask = (const int*)d_in[2];
    const float* Wr   = (const float*)d_in[3];
    const float* br   = (const float*)d_in[4];
    const float* Wu   = (const float*)d_in[5];
    const float* bu   = (const float*)d_in[6];
    const float* Wc   = (const float*)d_in[7];
    const float* bc   = (const float*)d_in[8];
    const float* Wo   = (const float*)d_in[9];
    const float* bo   = (const float*)d_in[10];
    float* out = (float*)d_out;

    cudaFuncSetAttribute(gx_mma_kernel, cudaFuncAttributeMaxDynamicSharedMemorySize,
                         GX_SMEM_BYTES);
    cudaFuncSetAttribute(gru2_kernel, cudaFuncAttributeMaxDynamicSharedMemorySize,
                         GRU_SMEM);

    prepw_kernel<<<2304, 256>>>(Wr, Wu, Wc);
    prepa_kernel<<<51200, 256>>>(hist);
    attn_kernel<<<NB, 256>>>(hist, tgt, mask);
    gx_mma_kernel<<<dim3(6, 1600), 256, GX_SMEM_BYTES>>>(br, bu, bc);
    gru2_kernel<<<64, 256, GRU_SMEM>>>(mask, Wo, bo, out);
}

// round 11
// speedup vs baseline: 2.3664x; 1.0389x over previous
#include <cuda_runtime.h>
#include <cuda_bf16.h>
#include <cstdint>
#include <math.h>

#define NB 1024
#define NS 200
#define NH 256
#define KTOT 768

// ---------------- scratch (device globals; no allocations allowed) ----------
static __device__ float g_att[NB * NS];                        // softmax attention [b][s]
static __device__ float g_gx[(size_t)NS * NB * 768];           // x-part preact [s][b][768]
static __device__ __nv_bfloat16 g_abf[(size_t)NB * NS * KTOT]; // A' = [Ah|Ah|Al] [m][768] (gx)
static __device__ __nv_bfloat16 g_bbf[768 * KTOT];             // B' = [Bh|Bl|Bh] [n][768] (gx)
static __device__ __nv_bfloat16 g_wruf[512 * 512];             // Whru' frag-layout K=512 (F=8)
static __device__ __nv_bfloat16 g_wcf[256 * 512];              // Whc'  frag-layout K=512 (F=4)

__device__ __forceinline__ float sig_(float x)  { return 1.0f / (1.0f + expf(-x)); }

__device__ __forceinline__ uint32_t smem_u32(const void* p) {
    uint32_t a;
    asm("{ .reg .u64 t; cvta.to.shared.u64 t, %1; cvt.u32.u64 %0, t; }" : "=r"(a) : "l"(p));
    return a;
}

#define CP_ASYNC16(dst, src) \
    asm volatile("cp.async.cg.shared.global [%0], [%1], 16;" :: "r"(dst), "l"(src))
#define CP_COMMIT() asm volatile("cp.async.commit_group;" ::: "memory")
#define CP_WAIT0()  asm volatile("cp.async.wait_group 0;" ::: "memory")
#define CP_WAIT1()  asm volatile("cp.async.wait_group 1;" ::: "memory")

#define LDSM4(r, addr)                                                            \
    asm volatile("ldmatrix.sync.aligned.m8n8.x4.shared.b16 {%0,%1,%2,%3}, [%4];"  \
                 : "=r"((r)[0]), "=r"((r)[1]), "=r"((r)[2]), "=r"((r)[3])         \
                 : "r"(addr))

#define MMA16816(d, a, b0, b1)                                                    \
    asm volatile("mma.sync.aligned.m16n8k16.row.col.f32.bf16.bf16.f32 "           \
                 "{%0,%1,%2,%3}, {%4,%5,%6,%7}, {%8,%9}, {%0,%1,%2,%3};"          \
                 : "+f"((d)[0]), "+f"((d)[1]), "+f"((d)[2]), "+f"((d)[3])         \
                 : "r"((a)[0]), "r"((a)[1]), "r"((a)[2]), "r"((a)[3]),            \
                   "r"(b0), "r"(b1))

// byte offset of weight element (n,k) in per-warp fragment layout
__device__ __forceinline__ uint32_t frag_off(int n, int k, int F, int sshift, int NT2) {
    int w = n >> sshift;
    int f = (n >> 3) & (F - 1);
    int r = n & 7;
    int t2 = k >> 5;
    int th = (k >> 4) & 1;
    int kk = k & 15;
    int lane = (r << 2) | ((kk & 7) >> 1);
    int byte = (th << 3) | (((kk >> 3) & 1) << 2) | ((kk & 1) << 1);
    return (uint32_t)(((((w * F + f) * NT2 + t2) * 32 + lane) << 4) + byte);
}

// swizzled byte offset within a 16x512-bf16 A-tile (1024B rows)
__device__ __forceinline__ uint32_t a_off(int m, int k) {
    int seg = k >> 3;
    int segs = (seg & ~7) | ((seg ^ m) & 7);
    return (uint32_t)(m * 1024 + segs * 16 + (k & 7) * 2);
}

__device__ __forceinline__ void bf16split(float x, __nv_bfloat16& h, __nv_bfloat16& l) {
    h = __float2bfloat16(x);
    l = __float2bfloat16(x - __bfloat162float(h));
}

// ---------------- K0a: weight packing ----------------------------------------
__global__ void prepw_kernel(const float* __restrict__ Wr, const float* __restrict__ Wu,
                             const float* __restrict__ Wc)
{
    int idx = blockIdx.x * blockDim.x + threadIdx.x;
    if (idx < 196608) {
        // gx B' = [Bh | Bl | Bh], [n][k] k-major (x-part cols 0..255) -- 3-term
        int n = idx >> 8, k = idx & 255;
        float v;
        if (n < 256)      v = Wr[n * 512 + k];
        else if (n < 512) v = Wu[(n - 256) * 512 + k];
        else              v = Wc[(n - 512) * 512 + k];
        __nv_bfloat16 hi, lo; bf16split(v, hi, lo);
        g_bbf[(size_t)n * KTOT + k]       = hi;
        g_bbf[(size_t)n * KTOT + 256 + k] = lo;
        g_bbf[(size_t)n * KTOT + 512 + k] = hi;
    } else if (idx < 196608 + 262144) {
        // Whru' frag layout, K-concat [hi | lo] (K=512), h-part cols 256..511
        int e = idx - 196608;
        int n = e >> 9, k = e & 511;
        int kk = k & 255;
        float v = (n < 256) ? Wr[n * 512 + 256 + kk] : Wu[(n - 256) * 512 + 256 + kk];
        __nv_bfloat16 hi, lo; bf16split(v, hi, lo);
        __nv_bfloat16 val = (k < 256) ? hi : lo;
        *(__nv_bfloat16*)((char*)g_wruf + frag_off(n, k, 8, 6, 16)) = val;
    } else if (idx < 196608 + 262144 + 131072) {
        int e = idx - (196608 + 262144);
        int n = e >> 9, k = e & 511;
        int kk = k & 255;
        float v = Wc[n * 512 + 256 + kk];
        __nv_bfloat16 hi, lo; bf16split(v, hi, lo);
        __nv_bfloat16 val = (k < 256) ? hi : lo;
        *(__nv_bfloat16*)((char*)g_wcf + frag_off(n, k, 4, 5, 16)) = val;
    }
}

// ---------------- K0b: hist -> A' = [Ah | Ah | Al] (gx, 3-term) ---------------
__global__ void __launch_bounds__(256) prepa_kernel(const float* __restrict__ hist)
{
    size_t i = (size_t)blockIdx.x * 256 + threadIdx.x;
    int m = (int)(i >> 6);
    int kq = ((int)i & 63) * 4;
    float4 v = *(const float4*)(hist + (size_t)m * 256 + kq);
    float x[4] = {v.x, v.y, v.z, v.w};
    __nv_bfloat16 h[4], l[4];
    #pragma unroll
    for (int j = 0; j < 4; j++) bf16split(x[j], h[j], l[j]);
    uint32_t hi01 = (uint32_t)__bfloat16_as_ushort(h[0]) | ((uint32_t)__bfloat16_as_ushort(h[1]) << 16);
    uint32_t hi23 = (uint32_t)__bfloat16_as_ushort(h[2]) | ((uint32_t)__bfloat16_as_ushort(h[3]) << 16);
    uint32_t lo01 = (uint32_t)__bfloat16_as_ushort(l[0]) | ((uint32_t)__bfloat16_as_ushort(l[1]) << 16);
    uint32_t lo23 = (uint32_t)__bfloat16_as_ushort(l[2]) | ((uint32_t)__bfloat16_as_ushort(l[3]) << 16);
    __nv_bfloat16* row = g_abf + (size_t)m * KTOT + kq;
    *(uint2*)(row)       = make_uint2(hi01, hi23);
    *(uint2*)(row + 256) = make_uint2(hi01, hi23);
    *(uint2*)(row + 512) = make_uint2(lo01, lo23);
}

// ---------------- K1: attention softmax --------------------------------------
__global__ void __launch_bounds__(256) attn_kernel(const float* __restrict__ hist,
                                                   const float* __restrict__ tgt,
                                                   const int* __restrict__ mask)
{
    __shared__ float tg[256];
    __shared__ float lg[200];
    __shared__ float red[8];
    int b = blockIdx.x;
    int t = threadIdx.x;
    int lane = t & 31, w = t >> 5;
    tg[t] = tgt[b * 256 + t];
    __syncthreads();
    for (int s = w; s < 200; s += 8) {
        const float* hp = hist + ((size_t)(b * 200 + s)) * 256;
        float acc = 0.0f;
        #pragma unroll
        for (int i = 0; i < 8; i++) acc += hp[lane + 32 * i] * tg[lane + 32 * i];
        #pragma unroll
        for (int o = 16; o > 0; o >>= 1) acc += __shfl_xor_sync(0xffffffffu, acc, o);
        if (lane == 0)
            lg[s] = (mask[b * 200 + s] == 0) ? -1.0e9f : acc * 0.0625f;
    }
    __syncthreads();
    float v = (t < 200) ? lg[t] : -3.0e38f;
    float m = v;
    #pragma unroll
    for (int o = 16; o > 0; o >>= 1) m = fmaxf(m, __shfl_xor_sync(0xffffffffu, m, o));
    if (lane == 0) red[w] = m;
    __syncthreads();
    if (t == 0) {
        float mm = red[0];
        for (int i = 1; i < 8; i++) mm = fmaxf(mm, red[i]);
        red[0] = mm;
    }
    __syncthreads();
    float mx = red[0];
    float e = (t < 200) ? expf(v - mx) : 0.0f;
    __syncthreads();
    float ssum = e;
    #pragma unroll
    for (int o = 16; o > 0; o >>= 1) ssum += __shfl_xor_sync(0xffffffffu, ssum, o);
    if (lane == 0) red[w] = ssum;
    __syncthreads();
    if (t == 0) {
        float tt = 0.0f;
        for (int i = 0; i < 8; i++) tt += red[i];
        red[0] = tt;
    }
    __syncthreads();
    if (t < 200) g_att[b * 200 + t] = e / red[0];
}

// ---------------- K2: Gx GEMM via mma.sync bf16, 3-term K=768 (proven) --------
static constexpr int GX_TILE_BYTES = 16384;
static constexpr int GX_BUF_BYTES  = 2 * GX_TILE_BYTES;
static constexpr int GX_SMEM_BYTES = 1024 + 2 * GX_BUF_BYTES;

__global__ void __launch_bounds__(256, 1) gx_mma_kernel(const float* __restrict__ br,
                                                        const float* __restrict__ bu,
                                                        const float* __restrict__ bc)
{
    extern __shared__ char sm[];
    float* bias_s = (float*)sm;
    char* tiles = sm + 1024;
    uint32_t tiles_u = smem_u32(tiles);

    int t = threadIdx.x;
    int lane = t & 31, wid = t >> 5;
    int n0 = blockIdx.x * 128;
    int m0 = blockIdx.y * 128;

    if (t < 128) {
        int n = n0 + t;
        bias_s[t] = (n < 256) ? br[n] : (n < 512) ? bu[n - 256] : bc[n - 512];
    }

    int lrow = t >> 3;
    int lc16 = t & 7;
    const __nv_bfloat16* gA = g_abf + (size_t)(m0 + lrow) * KTOT + lc16 * 8;
    const __nv_bfloat16* gB = g_bbf + (size_t)(n0 + lrow) * KTOT + lc16 * 8;
    uint32_t sA[4], sB[4];
    #pragma unroll
    for (int r = 0; r < 4; r++) {
        uint32_t off = (uint32_t)((lrow + r * 32) * 128 + lc16 * 16);
        off ^= (off >> 3) & 0x70;
        sA[r] = tiles_u + off;
        sB[r] = tiles_u + GX_TILE_BYTES + off;
    }

    int wm = (wid >> 2) * 64;
    int wn = (wid & 3) * 32;
    uint32_t aR[4], aX[4], bR[2], bX[2];
    #pragma unroll
    for (int mf = 0; mf < 4; mf++) {
        uint32_t R = (uint32_t)(wm + mf * 16 + (lane & 15)) * 128;
        aR[mf] = R; aX[mf] = (R >> 3) & 0x70;
    }
    #pragma unroll
    for (int nf2 = 0; nf2 < 2; nf2++) {
        uint32_t R = (uint32_t)(wn + nf2 * 16 + (lane & 15)) * 128;
        bR[nf2] = R; bX[nf2] = (R >> 3) & 0x70;
    }
    uint32_t Ckl = ((uint32_t)(lane >> 4)) << 4;

    float d[4][4][4];
    #pragma unroll
    for (int i = 0; i < 4; i++)
        #pragma unroll
        for (int j = 0; j < 4; j++)
            #pragma unroll
            for (int r = 0; r < 4; r++) d[i][j][r] = 0.0f;

    #pragma unroll
    for (int r = 0; r < 4; r++) {
        CP_ASYNC16(sA[r], gA + (size_t)(r * 32) * KTOT);
        CP_ASYNC16(sB[r], gB + (size_t)(r * 32) * KTOT);
    }
    CP_COMMIT();

    const int NCHUNK = KTOT / 64;
    for (int c = 0; c < NCHUNK; c++) {
        int buf = c & 1;
        if (c + 1 < NCHUNK) {
            uint32_t bo = (uint32_t)((buf ^ 1) * GX_BUF_BYTES);
            int kc = (c + 1) * 64;
            #pragma unroll
            for (int r = 0; r < 4; r++) {
                CP_ASYNC16(sA[r] + bo, gA + (size_t)(r * 32) * KTOT + kc);
                CP_ASYNC16(sB[r] + bo, gB + (size_t)(r * 32) * KTOT + kc);
            }
            CP_COMMIT();
            CP_WAIT1();
        } else {
            CP_WAIT0();
        }
        __syncthreads();
        uint32_t abase = tiles_u + (uint32_t)(buf * GX_BUF_BYTES);
        uint32_t bbase = abase + GX_TILE_BYTES;
        #pragma unroll
        for (int ks = 0; ks < 4; ks++) {
            uint32_t C = (uint32_t)(ks * 32) + Ckl;
            uint32_t a[4][4], bb[2][4];
            #pragma unroll
            for (int mf = 0; mf < 4; mf++)
                LDSM4(a[mf], abase + aR[mf] + (C ^ aX[mf]));
            #pragma unroll
            for (int nf2 = 0; nf2 < 2; nf2++)
                LDSM4(bb[nf2], bbase + bR[nf2] + (C ^ bX[nf2]));
            #pragma unroll
            for (int mf = 0; mf < 4; mf++) {
                #pragma unroll
                for (int nf = 0; nf < 4; nf++) {
                    uint32_t b0 = bb[nf >> 1][nf & 1];
                    uint32_t b1 = bb[nf >> 1][(nf & 1) + 2];
                    MMA16816(d[mf][nf], a[mf], b0, b1);
                }
            }
        }
        __syncthreads();
    }

    int groupID = lane >> 2;
    int tc = (lane & 3) * 2;
    #pragma unroll
    for (int mf = 0; mf < 4; mf++) {
        #pragma unroll
        for (int half = 0; half < 2; half++) {
            int m = m0 + wm + mf * 16 + groupID + half * 8;
            int b = m / 200, s = m - b * 200;
            float* dst = g_gx + ((size_t)s * NB + b) * 768 + n0 + wn;
            #pragma unroll
            for (int nf = 0; nf < 4; nf++) {
                float2 bi = *(float2*)&bias_s[wn + nf * 8 + tc];
                float2 o = make_float2(d[mf][nf][half * 2 + 0] + bi.x,
                                       d[mf][nf][half * 2 + 1] + bi.y);
                *(float2*)(dst + nf * 8 + tc) = o;
            }
        }
    }
}

// ---------------- K3: GRU scan via mma.sync (64 CTAs x 16 rows, K=512) --------
// smem: A1[0,16384) A2[16384,32768) h[32768,+16896) u[49664,+16896)
//       att[66560,+128) mask[66688,+128) gx slabs [66816, +2x49664)
static constexpr int HSTRIDE = 264;             // floats; 264 % 32 == 8 -> conflict-free
static constexpr int GXSTRIDE = 776;            // floats; 776 % 32 == 8
static constexpr int GRU_H_OFF   = 32768;
static constexpr int GRU_U_OFF   = 49664;
static constexpr int GRU_ATT_OFF = 66560;
static constexpr int GRU_MSK_OFF = 66688;
static constexpr int GRU_GX_OFF  = 66816;
static constexpr int GRU_GX_SLAB = 16 * GXSTRIDE * 4;   // 49664
static constexpr int GRU_SMEM = GRU_GX_OFF + 2 * GRU_GX_SLAB;  // 166144

// K=512 fragment GEMM: acc[F][4] += A(smem,swizzled) x B(global frag layout)
template<int F>
__device__ __forceinline__ void gemm_frag(uint32_t Abase, const char* pw,
                                          int lane, float acc[][4])
{
    uint4 Bb[3][F];
    #pragma unroll
    for (int p = 0; p < 2; p++)
        #pragma unroll
        for (int f = 0; f < F; f++)
            Bb[p][f] = *(const uint4*)(pw + (f * 16 + p) * 512);
    #pragma unroll
    for (int t2 = 0; t2 < 16; t2++) {
        if (t2 < 14) {
            #pragma unroll
            for (int f = 0; f < F; f++)
                Bb[(t2 + 2) % 3][f] = *(const uint4*)(pw + (f * 16 + t2 + 2) * 512);
        }
        #pragma unroll
        for (int th = 0; th < 2; th++) {
            int row = lane & 15;
            int seg = 4 * t2 + 2 * th + (lane >> 4);
            uint32_t aaddr = Abase + (uint32_t)(row * 1024)
                           + (uint32_t)(((seg & ~7) | ((seg ^ row) & 7)) << 4);
            uint32_t a[4];
            LDSM4(a, aaddr);
            #pragma unroll
            for (int f = 0; f < F; f++) {
                if (th == 0) MMA16816(acc[f], a, Bb[t2 % 3][f].x, Bb[t2 % 3][f].y);
                else         MMA16816(acc[f], a, Bb[t2 % 3][f].z, Bb[t2 % 3][f].w);
            }
        }
    }
}

__global__ void __launch_bounds__(256, 1) gru2_kernel(const int* __restrict__ mask,
                                                      const float* __restrict__ Wo,
                                                      const float* __restrict__ bo,
                                                      float* __restrict__ out)
{
    extern __shared__ char smx[];
    uint32_t a1u = smem_u32(smx);
    uint32_t a2u = a1u + 16384;
    float* h_sF = (float*)(smx + GRU_H_OFF);
    float* u_sF = (float*)(smx + GRU_U_OFF);
    float* a_sF = (float*)(smx + GRU_ATT_OFF);   // [2][16] parity-buffered
    int*   m_sI = (int*)(smx + GRU_MSK_OFF);     // [2][16] parity-buffered

    int b0 = blockIdx.x * 16;
    int t = threadIdx.x;
    int lane = t & 31, wid = t >> 5;
    int g = lane >> 2, tc = (lane & 3) * 2;

    const char* pw1 = (const char*)g_wruf + wid * 65536 + lane * 16;
    const char* pw2 = (const char*)g_wcf + wid * 32768 + lane * 16;

    // zero A1 (h=0 tile) + h
    #pragma unroll
    for (int i = 0; i < 16; i++) ((uint32_t*)smx)[t + i * 256] = 0u;
    for (int i = t; i < 16 * HSTRIDE; i += 256) h_sF[i] = 0.0f;
    if (t < 16) {
        a_sF[t] = g_att[(b0 + t) * NS];
        m_sI[t] = mask[(b0 + t) * NS];
    }
    // prologue: stage gx slab 0
    {
        const char* src = (const char*)(g_gx + (size_t)b0 * 768);
        uint32_t dstb = a1u + GRU_GX_OFF;
        #pragma unroll
        for (int rep = 0; rep < 12; rep++) {
            int u = t + rep * 256;
            int row = u / 192, col = u - row * 192;
            CP_ASYNC16(dstb + (uint32_t)(row * (GXSTRIDE * 4) + col * 16),
                       src + row * 3072 + col * 16);
        }
        CP_COMMIT();
        CP_WAIT0();
    }
    float pool[4][4];
    #pragma unroll
    for (int f = 0; f < 4; f++)
        #pragma unroll
        for (int i = 0; i < 4; i++) pool[f][i] = -3.0e38f;
    __syncthreads();

    #pragma unroll 1
    for (int s = 0; s < 200; s++) {
        int par = s & 1, nxt = par ^ 1;
        const float* gxs = (const float*)(smx + GRU_GX_OFF + par * GRU_GX_SLAB);

        // ---- GEMM1: preact_ru = gx + h @ Whru'^T  (acc init from smem slab)
        float acc[8][4];
        #pragma unroll
        for (int f = 0; f < 8; f++) {
            int nidx = wid * 64 + f * 8 + tc;
            float2 v0 = *(const float2*)(gxs + g * GXSTRIDE + nidx);
            float2 v1 = *(const float2*)(gxs + (g + 8) * GXSTRIDE + nidx);
            acc[f][0] = v0.x; acc[f][1] = v0.y; acc[f][2] = v1.x; acc[f][3] = v1.y;
        }

        // prefetch next gx slab (overlaps both GEMMs; waited at end of step)
        if (s + 1 < 200) {
            const char* src = (const char*)(g_gx + ((size_t)(s + 1) * NB + b0) * 768);
            uint32_t dstb = a1u + GRU_GX_OFF + (uint32_t)(nxt * GRU_GX_SLAB);
            #pragma unroll
            for (int rep = 0; rep < 12; rep++) {
                int u = t + rep * 256;
                int row = u / 192, col = u - row * 192;
                CP_ASYNC16(dstb + (uint32_t)(row * (GXSTRIDE * 4) + col * 16),
                           src + row * 3072 + col * 16);
            }
            CP_COMMIT();
        }

        gemm_frag<8>(a1u, pw1, lane, acc);

        // prefetch next att/mask into OTHER parity buffer (race-free)
        if (t < 16 && s + 1 < 200) {
            a_sF[nxt * 16 + t] = g_att[(b0 + t) * NS + s + 1];
            m_sI[nxt * 16 + t] = mask[(b0 + t) * NS + s + 1];
        }

        // ---- gates: r -> rh into A2 ; u' = a*u into u_s
        if (wid < 4) {
            #pragma unroll
            for (int f = 0; f < 8; f++) {
                int j = wid * 64 + f * 8 + tc;
                #pragma unroll
                for (int half = 0; half < 2; half++) {
                    int m = half * 8 + g;
                    float r0 = sig_(acc[f][half * 2 + 0]);
                    float r1 = sig_(acc[f][half * 2 + 1]);
                    float2 hh = *(float2*)(h_sF + m * HSTRIDE + j);
                    __nv_bfloat16 h0 = __float2bfloat16(r0 * hh.x);
                    __nv_bfloat16 h1 = __float2bfloat16(r1 * hh.y);
                    uint32_t hp = (uint32_t)__bfloat16_as_ushort(h0) |
                                  ((uint32_t)__bfloat16_as_ushort(h1) << 16);
                    *(uint32_t*)(smx + 16384 + a_off(m, j))       = hp;
                    *(uint32_t*)(smx + 16384 + a_off(m, 256 + j)) = hp;
                }
            }
        } else {
            #pragma unroll
            for (int f = 0; f < 8; f++) {
                int j = (wid - 4) * 64 + f * 8 + tc;
                #pragma unroll
                for (int half = 0; half < 2; half++) {
                    int m = half * 8 + g;
                    float am = a_sF[par * 16 + m];
                    float u0 = sig_(acc[f][half * 2 + 0]) * am;
                    float u1 = sig_(acc[f][half * 2 + 1]) * am;
                    *(float2*)(u_sF + m * HSTRIDE + j) = make_float2(u0, u1);
                }
            }
        }
        __syncthreads();

        // ---- GEMM2: preact_c = gx_c + rh @ Whc'^T
        float acc2[4][4];
        #pragma unroll
        for (int f = 0; f < 4; f++) {
            int nidx = 512 + wid * 32 + f * 8 + tc;
            float2 v0 = *(const float2*)(gxs + g * GXSTRIDE + nidx);
            float2 v1 = *(const float2*)(gxs + (g + 8) * GXSTRIDE + nidx);
            acc2[f][0] = v0.x; acc2[f][1] = v0.y; acc2[f][2] = v1.x; acc2[f][3] = v1.y;
        }
        gemm_frag<4>(a2u, pw2, lane, acc2);

        // ---- update: h += u'*(tanh(pre_c) - h); pool; write h fp32 + A1 bf16
        #pragma unroll
        for (int f = 0; f < 4; f++) {
            int j2 = wid * 32 + f * 8 + tc;
            #pragma unroll
            for (int half = 0; half < 2; half++) {
                int m = half * 8 + g;
                float c0 = tanhf(acc2[f][half * 2 + 0]);
                float c1 = tanhf(acc2[f][half * 2 + 1]);
                float2 uu = *(float2*)(u_sF + m * HSTRIDE + j2);
                float2 hh = *(float2*)(h_sF + m * HSTRIDE + j2);
                float hn0 = hh.x + uu.x * (c0 - hh.x);
                float hn1 = hh.y + uu.y * (c1 - hh.y);
                *(float2*)(h_sF + m * HSTRIDE + j2) = make_float2(hn0, hn1);
                int mk = m_sI[par * 16 + m];
                pool[f][half * 2 + 0] = fmaxf(pool[f][half * 2 + 0], mk ? hn0 : 0.0f);
                pool[f][half * 2 + 1] = fmaxf(pool[f][half * 2 + 1], mk ? hn1 : 0.0f);
                __nv_bfloat16 h0 = __float2bfloat16(hn0);
                __nv_bfloat16 h1 = __float2bfloat16(hn1);
                uint32_t hp = (uint32_t)__bfloat16_as_ushort(h0) |
                              ((uint32_t)__bfloat16_as_ushort(h1) << 16);
                *(uint32_t*)(smx + a_off(m, j2))       = hp;
                *(uint32_t*)(smx + a_off(m, 256 + j2)) = hp;
            }
        }
        CP_WAIT0();          // next gx slab landed (no-op at s=199)
        __syncthreads();
    }

    // ---- epilogue: pooled -> u_s, then out = [h_last | pooled @ Wo^T + bo]
    #pragma unroll
    for (int f = 0; f < 4; f++) {
        int j2 = wid * 32 + f * 8 + tc;
        #pragma unroll
        for (int half = 0; half < 2; half++) {
            int m = half * 8 + g;
            *(float2*)(u_sF + m * HSTRIDE + j2) =
                make_float2(pool[f][half * 2 + 0], pool[f][half * 2 + 1]);
        }
    }
    __syncthreads();

    #pragma unroll
    for (int m = 0; m < 16; m++)
        out[(size_t)(b0 + m) * 512 + t] = h_sF[m * HSTRIDE + t];

    float wacc[16];
    #pragma unroll
    for (int m = 0; m < 16; m++) wacc[m] = 0.0f;
    #pragma unroll 4
    for (int k = 0; k < 256; k++) {
        float wv = Wo[t * 256 + k];
        #pragma unroll
        for (int m = 0; m < 16; m++) wacc[m] += u_sF[m * HSTRIDE + k] * wv;
    }
    float bb = bo[t];
    #pragma unroll
    for (int m = 0; m < 16; m++)
        out[(size_t)(b0 + m) * 512 + 256 + t] = wacc[m] + bb;
}

// ---------------- launch ------------------------------------------------------
extern "C" void kernel_launch(void* const* d_in, const int* in_sizes, int n_in,
                              void* d_out, int out_size)
{
    const float* hist = (const float*)d_in[0];
    const float* tgt  = (const float*)d_in[1];
    const int*   mask = (const int*)d_in[2];
    const float* Wr   = (const float*)d_in[3];
    const float* br   = (const float*)d_in[4];
    const float* Wu   = (const float*)d_in[5];
    const float* bu   = (const float*)d_in[6];
    const float* Wc   = (const float*)d_in[7];
    const float* bc   = (const float*)d_in[8];
    const float* Wo   = (const float*)d_in[9];
    const float* bo   = (const float*)d_in[10];
    float* out = (float*)d_out;

    cudaFuncSetAttribute(gx_mma_kernel, cudaFuncAttributeMaxDynamicSharedMemorySize,
                         GX_SMEM_BYTES);
    cudaFuncSetAttribute(gru2_kernel, cudaFuncAttributeMaxDynamicSharedMemorySize,
                         GRU_SMEM);

    prepw_kernel<<<2304, 256>>>(Wr, Wu, Wc);
    prepa_kernel<<<51200, 256>>>(hist);
    attn_kernel<<<NB, 256>>>(hist, tgt, mask);
    gx_mma_kernel<<<dim3(6, 1600), 256, GX_SMEM_BYTES>>>(br, bu, bc);
    gru2_kernel<<<64, 256, GRU_SMEM>>>(mask, Wo, bo, out);
}

// round 14
// speedup vs baseline: 2.6576x; 1.1231x over previous
#include <cuda_runtime.h>
#include <cuda_bf16.h>
#include <cstdint>
#include <math.h>

#define NB 1024
#define NS 200
#define NH 256
#define KTOT 768

// ---------------- scratch (device globals; no allocations allowed) ----------
static __device__ float g_att[NB * NS];                        // softmax attention [b][s]
static __device__ float g_gx[(size_t)NS * NB * 768];           // x-part preact [s][b][768]
static __device__ __nv_bfloat16 g_abf[(size_t)NB * NS * KTOT]; // A' = [Ah|Ah|Al] [m][768] (gx)
static __device__ __nv_bfloat16 g_bbf[768 * KTOT];             // B' = [Bh|Bl|Bh] [n][768] (gx)
static __device__ __nv_bfloat16 g_wruf[512 * 512];             // Whru' frag-layout K=512 (16w,F=4)
static __device__ __nv_bfloat16 g_wcf[256 * 512];              // Whc'  frag-layout K=512 (16w,F=2)

__device__ __forceinline__ float sigf_(float x) {
    return __fdividef(1.0f, 1.0f + __expf(-x));
}
__device__ __forceinline__ float tanhf_(float x) {
    return __fdividef(2.0f, 1.0f + __expf(-2.0f * x)) - 1.0f;
}

__device__ __forceinline__ uint32_t smem_u32(const void* p) {
    uint32_t a;
    asm("{ .reg .u64 t; cvta.to.shared.u64 t, %1; cvt.u32.u64 %0, t; }" : "=r"(a) : "l"(p));
    return a;
}

#define CP_ASYNC16(dst, src) \
    asm volatile("cp.async.cg.shared.global [%0], [%1], 16;" :: "r"(dst), "l"(src))
#define CP_COMMIT() asm volatile("cp.async.commit_group;" ::: "memory")
#define CP_WAIT0()  asm volatile("cp.async.wait_group 0;" ::: "memory")
#define CP_WAIT1()  asm volatile("cp.async.wait_group 1;" ::: "memory")

#define LDSM4(r, addr)                                                            \
    asm volatile("ldmatrix.sync.aligned.m8n8.x4.shared.b16 {%0,%1,%2,%3}, [%4];"  \
                 : "=r"((r)[0]), "=r"((r)[1]), "=r"((r)[2]), "=r"((r)[3])         \
                 : "r"(addr))

#define MMA16816(d, a, b0, b1)                                                    \
    asm volatile("mma.sync.aligned.m16n8k16.row.col.f32.bf16.bf16.f32 "           \
                 "{%0,%1,%2,%3}, {%4,%5,%6,%7}, {%8,%9}, {%0,%1,%2,%3};"          \
                 : "+f"((d)[0]), "+f"((d)[1]), "+f"((d)[2]), "+f"((d)[3])         \
                 : "r"((a)[0]), "r"((a)[1]), "r"((a)[2]), "r"((a)[3]),            \
                   "r"(b0), "r"(b1))

// byte offset of weight element (n,k) in per-warp fragment layout
__device__ __forceinline__ uint32_t frag_off(int n, int k, int F, int sshift, int NT2) {
    int w = n >> sshift;
    int f = (n >> 3) & (F - 1);
    int r = n & 7;
    int t2 = k >> 5;
    int th = (k >> 4) & 1;
    int kk = k & 15;
    int lane = (r << 2) | ((kk & 7) >> 1);
    int byte = (th << 3) | (((kk >> 3) & 1) << 2) | ((kk & 1) << 1);
    return (uint32_t)(((((w * F + f) * NT2 + t2) * 32 + lane) << 4) + byte);
}

// swizzled byte offset within a 16x512-bf16 A-tile (1024B rows)
__device__ __forceinline__ uint32_t a_off(int m, int k) {
    int seg = k >> 3;
    int segs = (seg & ~7) | ((seg ^ m) & 7);
    return (uint32_t)(m * 1024 + segs * 16 + (k & 7) * 2);
}

__device__ __forceinline__ void bf16split(float x, __nv_bfloat16& h, __nv_bfloat16& l) {
    h = __float2bfloat16(x);
    l = __float2bfloat16(x - __bfloat162float(h));
}

// ---------------- K0a: weight packing ----------------------------------------
__global__ void prepw_kernel(const float* __restrict__ Wr, const float* __restrict__ Wu,
                             const float* __restrict__ Wc)
{
    int idx = blockIdx.x * blockDim.x + threadIdx.x;
    if (idx < 196608) {
        // gx B' = [Bh | Bl | Bh], [n][k] k-major (x-part cols 0..255) -- 3-term
        int n = idx >> 8, k = idx & 255;
        float v;
        if (n < 256)      v = Wr[n * 512 + k];
        else if (n < 512) v = Wu[(n - 256) * 512 + k];
        else              v = Wc[(n - 512) * 512 + k];
        __nv_bfloat16 hi, lo; bf16split(v, hi, lo);
        g_bbf[(size_t)n * KTOT + k]       = hi;
        g_bbf[(size_t)n * KTOT + 256 + k] = lo;
        g_bbf[(size_t)n * KTOT + 512 + k] = hi;
    } else if (idx < 196608 + 262144) {
        // Whru' frag layout for 16-warp scan (F=4, 32 n/warp), K-concat [hi|lo]
        int e = idx - 196608;
        int n = e >> 9, k = e & 511;
        int kk = k & 255;
        float v = (n < 256) ? Wr[n * 512 + 256 + kk] : Wu[(n - 256) * 512 + 256 + kk];
        __nv_bfloat16 hi, lo; bf16split(v, hi, lo);
        __nv_bfloat16 val = (k < 256) ? hi : lo;
        *(__nv_bfloat16*)((char*)g_wruf + frag_off(n, k, 4, 5, 16)) = val;
    } else if (idx < 196608 + 262144 + 131072) {
        // Whc' frag layout for 16-warp scan (F=2, 16 n/warp)
        int e = idx - (196608 + 262144);
        int n = e >> 9, k = e & 511;
        int kk = k & 255;
        float v = Wc[n * 512 + 256 + kk];
        __nv_bfloat16 hi, lo; bf16split(v, hi, lo);
        __nv_bfloat16 val = (k < 256) ? hi : lo;
        *(__nv_bfloat16*)((char*)g_wcf + frag_off(n, k, 2, 4, 16)) = val;
    }
}

// ---------------- K0b: hist -> A' = [Ah | Ah | Al] (gx, 3-term) ---------------
__global__ void __launch_bounds__(256) prepa_kernel(const float* __restrict__ hist)
{
    size_t i = (size_t)blockIdx.x * 256 + threadIdx.x;
    int m = (int)(i >> 6);
    int kq = ((int)i & 63) * 4;
    float4 v = *(const float4*)(hist + (size_t)m * 256 + kq);
    float x[4] = {v.x, v.y, v.z, v.w};
    __nv_bfloat16 h[4], l[4];
    #pragma unroll
    for (int j = 0; j < 4; j++) bf16split(x[j], h[j], l[j]);
    uint32_t hi01 = (uint32_t)__bfloat16_as_ushort(h[0]) | ((uint32_t)__bfloat16_as_ushort(h[1]) << 16);
    uint32_t hi23 = (uint32_t)__bfloat16_as_ushort(h[2]) | ((uint32_t)__bfloat16_as_ushort(h[3]) << 16);
    uint32_t lo01 = (uint32_t)__bfloat16_as_ushort(l[0]) | ((uint32_t)__bfloat16_as_ushort(l[1]) << 16);
    uint32_t lo23 = (uint32_t)__bfloat16_as_ushort(l[2]) | ((uint32_t)__bfloat16_as_ushort(l[3]) << 16);
    __nv_bfloat16* row = g_abf + (size_t)m * KTOT + kq;
    *(uint2*)(row)       = make_uint2(hi01, hi23);
    *(uint2*)(row + 256) = make_uint2(hi01, hi23);
    *(uint2*)(row + 512) = make_uint2(lo01, lo23);
}

// ---------------- K1: attention softmax --------------------------------------
__global__ void __launch_bounds__(256) attn_kernel(const float* __restrict__ hist,
                                                   const float* __restrict__ tgt,
                                                   const int* __restrict__ mask)
{
    __shared__ float tg[256];
    __shared__ float lg[200];
    __shared__ float red[8];
    int b = blockIdx.x;
    int t = threadIdx.x;
    int lane = t & 31, w = t >> 5;
    tg[t] = tgt[b * 256 + t];
    __syncthreads();
    for (int s = w; s < 200; s += 8) {
        const float* hp = hist + ((size_t)(b * 200 + s)) * 256;
        float acc = 0.0f;
        #pragma unroll
        for (int i = 0; i < 8; i++) acc += hp[lane + 32 * i] * tg[lane + 32 * i];
        #pragma unroll
        for (int o = 16; o > 0; o >>= 1) acc += __shfl_xor_sync(0xffffffffu, acc, o);
        if (lane == 0)
            lg[s] = (mask[b * 200 + s] == 0) ? -1.0e9f : acc * 0.0625f;
    }
    __syncthreads();
    float v = (t < 200) ? lg[t] : -3.0e38f;
    float m = v;
    #pragma unroll
    for (int o = 16; o > 0; o >>= 1) m = fmaxf(m, __shfl_xor_sync(0xffffffffu, m, o));
    if (lane == 0) red[w] = m;
    __syncthreads();
    if (t == 0) {
        float mm = red[0];
        for (int i = 1; i < 8; i++) mm = fmaxf(mm, red[i]);
        red[0] = mm;
    }
    __syncthreads();
    float mx = red[0];
    float e = (t < 200) ? expf(v - mx) : 0.0f;
    __syncthreads();
    float ssum = e;
    #pragma unroll
    for (int o = 16; o > 0; o >>= 1) ssum += __shfl_xor_sync(0xffffffffu, ssum, o);
    if (lane == 0) red[w] = ssum;
    __syncthreads();
    if (t == 0) {
        float tt = 0.0f;
        for (int i = 0; i < 8; i++) tt += red[i];
        red[0] = tt;
    }
    __syncthreads();
    if (t < 200) g_att[b * 200 + t] = e / red[0];
}

// ---------------- K2: Gx GEMM via mma.sync bf16, 3-term K=768 (proven) --------
static constexpr int GX_TILE_BYTES = 16384;
static constexpr int GX_BUF_BYTES  = 2 * GX_TILE_BYTES;
static constexpr int GX_SMEM_BYTES = 1024 + 2 * GX_BUF_BYTES;

__global__ void __launch_bounds__(256, 1) gx_mma_kernel(const float* __restrict__ br,
                                                        const float* __restrict__ bu,
                                                        const float* __restrict__ bc)
{
    extern __shared__ char sm[];
    float* bias_s = (float*)sm;
    char* tiles = sm + 1024;
    uint32_t tiles_u = smem_u32(tiles);

    int t = threadIdx.x;
    int lane = t & 31, wid = t >> 5;
    int n0 = blockIdx.x * 128;
    int m0 = blockIdx.y * 128;

    if (t < 128) {
        int n = n0 + t;
        bias_s[t] = (n < 256) ? br[n] : (n < 512) ? bu[n - 256] : bc[n - 512];
    }

    int lrow = t >> 3;
    int lc16 = t & 7;
    const __nv_bfloat16* gA = g_abf + (size_t)(m0 + lrow) * KTOT + lc16 * 8;
    const __nv_bfloat16* gB = g_bbf + (size_t)(n0 + lrow) * KTOT + lc16 * 8;
    uint32_t sA[4], sB[4];
    #pragma unroll
    for (int r = 0; r < 4; r++) {
        uint32_t off = (uint32_t)((lrow + r * 32) * 128 + lc16 * 16);
        off ^= (off >> 3) & 0x70;
        sA[r] = tiles_u + off;
        sB[r] = tiles_u + GX_TILE_BYTES + off;
    }

    int wm = (wid >> 2) * 64;
    int wn = (wid & 3) * 32;
    uint32_t aR[4], aX[4], bR[2], bX[2];
    #pragma unroll
    for (int mf = 0; mf < 4; mf++) {
        uint32_t R = (uint32_t)(wm + mf * 16 + (lane & 15)) * 128;
        aR[mf] = R; aX[mf] = (R >> 3) & 0x70;
    }
    #pragma unroll
    for (int nf2 = 0; nf2 < 2; nf2++) {
        uint32_t R = (uint32_t)(wn + nf2 * 16 + (lane & 15)) * 128;
        bR[nf2] = R; bX[nf2] = (R >> 3) & 0x70;
    }
    uint32_t Ckl = ((uint32_t)(lane >> 4)) << 4;

    float d[4][4][4];
    #pragma unroll
    for (int i = 0; i < 4; i++)
        #pragma unroll
        for (int j = 0; j < 4; j++)
            #pragma unroll
            for (int r = 0; r < 4; r++) d[i][j][r] = 0.0f;

    #pragma unroll
    for (int r = 0; r < 4; r++) {
        CP_ASYNC16(sA[r], gA + (size_t)(r * 32) * KTOT);
        CP_ASYNC16(sB[r], gB + (size_t)(r * 32) * KTOT);
    }
    CP_COMMIT();

    const int NCHUNK = KTOT / 64;
    for (int c = 0; c < NCHUNK; c++) {
        int buf = c & 1;
        if (c + 1 < NCHUNK) {
            uint32_t bo = (uint32_t)((buf ^ 1) * GX_BUF_BYTES);
            int kc = (c + 1) * 64;
            #pragma unroll
            for (int r = 0; r < 4; r++) {
                CP_ASYNC16(sA[r] + bo, gA + (size_t)(r * 32) * KTOT + kc);
                CP_ASYNC16(sB[r] + bo, gB + (size_t)(r * 32) * KTOT + kc);
            }
            CP_COMMIT();
            CP_WAIT1();
        } else {
            CP_WAIT0();
        }
        __syncthreads();
        uint32_t abase = tiles_u + (uint32_t)(buf * GX_BUF_BYTES);
        uint32_t bbase = abase + GX_TILE_BYTES;
        #pragma unroll
        for (int ks = 0; ks < 4; ks++) {
            uint32_t C = (uint32_t)(ks * 32) + Ckl;
            uint32_t a[4][4], bb[2][4];
            #pragma unroll
            for (int mf = 0; mf < 4; mf++)
                LDSM4(a[mf], abase + aR[mf] + (C ^ aX[mf]));
            #pragma unroll
            for (int nf2 = 0; nf2 < 2; nf2++)
                LDSM4(bb[nf2], bbase + bR[nf2] + (C ^ bX[nf2]));
            #pragma unroll
            for (int mf = 0; mf < 4; mf++) {
                #pragma unroll
                for (int nf = 0; nf < 4; nf++) {
                    uint32_t b0 = bb[nf >> 1][nf & 1];
                    uint32_t b1 = bb[nf >> 1][(nf & 1) + 2];
                    MMA16816(d[mf][nf], a[mf], b0, b1);
                }
            }
        }
        __syncthreads();
    }

    int groupID = lane >> 2;
    int tc = (lane & 3) * 2;
    #pragma unroll
    for (int mf = 0; mf < 4; mf++) {
        #pragma unroll
        for (int half = 0; half < 2; half++) {
            int m = m0 + wm + mf * 16 + groupID + half * 8;
            int b = m / 200, s = m - b * 200;
            float* dst = g_gx + ((size_t)s * NB + b) * 768 + n0 + wn;
            #pragma unroll
            for (int nf = 0; nf < 4; nf++) {
                float2 bi = *(float2*)&bias_s[wn + nf * 8 + tc];
                float2 o = make_float2(d[mf][nf][half * 2 + 0] + bi.x,
                                       d[mf][nf][half * 2 + 1] + bi.y);
                *(float2*)(dst + nf * 8 + tc) = o;
            }
        }
    }
}

// ---------------- K3: GRU scan via mma.sync (64 CTAs x 16 rows, 512 thr) ------
// smem: A1[0,16384) A2[16384,32768) h[32768,+16896) u[49664,+16896)
//       att[66560,+128) mask[66688,+128) gx slabs [66816, +2x49664)
static constexpr int HSTRIDE = 264;             // floats; 264 % 32 == 8 -> conflict-free
static constexpr int GXSTRIDE = 776;            // floats; 776 % 32 == 8
static constexpr int GRU_H_OFF   = 32768;
static constexpr int GRU_U_OFF   = 49664;
static constexpr int GRU_ATT_OFF = 66560;
static constexpr int GRU_MSK_OFF = 66688;
static constexpr int GRU_GX_OFF  = 66816;
static constexpr int GRU_GX_SLAB = 16 * GXSTRIDE * 4;   // 49664
static constexpr int GRU_SMEM = GRU_GX_OFF + 2 * GRU_GX_SLAB;  // 166144

// K=512 fragment GEMM: acc[F][4] += A(smem,swizzled) x B(global frag layout)
template<int F>
__device__ __forceinline__ void gemm_frag(uint32_t Abase, const char* pw,
                                          int lane, float acc[][4])
{
    uint4 Bb[3][F];
    #pragma unroll
    for (int p = 0; p < 2; p++)
        #pragma unroll
        for (int f = 0; f < F; f++)
            Bb[p][f] = *(const uint4*)(pw + (f * 16 + p) * 512);
    #pragma unroll
    for (int t2 = 0; t2 < 16; t2++) {
        if (t2 < 14) {
            #pragma unroll
            for (int f = 0; f < F; f++)
                Bb[(t2 + 2) % 3][f] = *(const uint4*)(pw + (f * 16 + t2 + 2) * 512);
        }
        #pragma unroll
        for (int th = 0; th < 2; th++) {
            int row = lane & 15;
            int seg = 4 * t2 + 2 * th + (lane >> 4);
            uint32_t aaddr = Abase + (uint32_t)(row * 1024)
                           + (uint32_t)(((seg & ~7) | ((seg ^ row) & 7)) << 4);
            uint32_t a[4];
            LDSM4(a, aaddr);
            #pragma unroll
            for (int f = 0; f < F; f++) {
                if (th == 0) MMA16816(acc[f], a, Bb[t2 % 3][f].x, Bb[t2 % 3][f].y);
                else         MMA16816(acc[f], a, Bb[t2 % 3][f].z, Bb[t2 % 3][f].w);
            }
        }
    }
}

__global__ void __launch_bounds__(512, 1) gru2_kernel(const int* __restrict__ mask,
                                                      const float* __restrict__ Wo,
                                                      const float* __restrict__ bo,
                                                      float* __restrict__ out)
{
    extern __shared__ char smx[];
    uint32_t a1u = smem_u32(smx);
    uint32_t a2u = a1u + 16384;
    float* h_sF = (float*)(smx + GRU_H_OFF);
    float* u_sF = (float*)(smx + GRU_U_OFF);
    float* a_sF = (float*)(smx + GRU_ATT_OFF);   // [2][16] parity-buffered
    int*   m_sI = (int*)(smx + GRU_MSK_OFF);     // [2][16] parity-buffered

    int b0 = blockIdx.x * 16;
    int t = threadIdx.x;
    int lane = t & 31, wid = t >> 5;              // wid 0..15
    int g = lane >> 2, tc = (lane & 3) * 2;

    const char* pw1 = (const char*)g_wruf + wid * 32768 + lane * 16;  // F=4 slice
    const char* pw2 = (const char*)g_wcf + wid * 16384 + lane * 16;   // F=2 slice

    // zero A1 (h=0 tile) + h
    #pragma unroll
    for (int i = 0; i < 8; i++) ((uint32_t*)smx)[t + i * 512] = 0u;
    for (int i = t; i < 16 * HSTRIDE; i += 512) h_sF[i] = 0.0f;
    if (t < 16) {
        a_sF[t] = g_att[(b0 + t) * NS];
        m_sI[t] = mask[(b0 + t) * NS];
    }
    // prologue: stage gx slab 0
    {
        const char* src = (const char*)(g_gx + (size_t)b0 * 768);
        uint32_t dstb = a1u + GRU_GX_OFF;
        #pragma unroll
        for (int rep = 0; rep < 6; rep++) {
            int u = t + rep * 512;
            int row = u / 192, col = u - row * 192;
            CP_ASYNC16(dstb + (uint32_t)(row * (GXSTRIDE * 4) + col * 16),
                       src + row * 3072 + col * 16);
        }
        CP_COMMIT();
        CP_WAIT0();
    }
    float pool[2][4];
    #pragma unroll
    for (int f = 0; f < 2; f++)
        #pragma unroll
        for (int i = 0; i < 4; i++) pool[f][i] = -3.0e38f;
    __syncthreads();

    #pragma unroll 1
    for (int s = 0; s < 200; s++) {
        int par = s & 1, nxt = par ^ 1;
        const float* gxs = (const float*)(smx + GRU_GX_OFF + par * GRU_GX_SLAB);

        // ---- GEMM1: preact_ru = gx + h @ Whru'^T  (acc init from smem slab)
        float acc[4][4];
        #pragma unroll
        for (int f = 0; f < 4; f++) {
            int nidx = wid * 32 + f * 8 + tc;
            float2 v0 = *(const float2*)(gxs + g * GXSTRIDE + nidx);
            float2 v1 = *(const float2*)(gxs + (g + 8) * GXSTRIDE + nidx);
            acc[f][0] = v0.x; acc[f][1] = v0.y; acc[f][2] = v1.x; acc[f][3] = v1.y;
        }

        // prefetch next gx slab (overlaps both GEMMs; waited at end of step)
        if (s + 1 < 200) {
            const char* src = (const char*)(g_gx + ((size_t)(s + 1) * NB + b0) * 768);
            uint32_t dstb = a1u + GRU_GX_OFF + (uint32_t)(nxt * GRU_GX_SLAB);
            #pragma unroll
            for (int rep = 0; rep < 6; rep++) {
                int u = t + rep * 512;
                int row = u / 192, col = u - row * 192;
                CP_ASYNC16(dstb + (uint32_t)(row * (GXSTRIDE * 4) + col * 16),
                           src + row * 3072 + col * 16);
            }
            CP_COMMIT();
        }

        gemm_frag<4>(a1u, pw1, lane, acc);

        // prefetch next att/mask into OTHER parity buffer (race-free)
        if (t < 16 && s + 1 < 200) {
            a_sF[nxt * 16 + t] = g_att[(b0 + t) * NS + s + 1];
            m_sI[nxt * 16 + t] = mask[(b0 + t) * NS + s + 1];
        }

        // ---- gates: warps 0-7: r -> rh into A2 ; warps 8-15: u' = a*u into u_s
        if (wid < 8) {
            #pragma unroll
            for (int f = 0; f < 4; f++) {
                int j = wid * 32 + f * 8 + tc;
                #pragma unroll
                for (int half = 0; half < 2; half++) {
                    int m = half * 8 + g;
                    float r0 = sigf_(acc[f][half * 2 + 0]);
                    float r1 = sigf_(acc[f][half * 2 + 1]);
                    float2 hh = *(float2*)(h_sF + m * HSTRIDE + j);
                    __nv_bfloat16 h0 = __float2bfloat16(r0 * hh.x);
                    __nv_bfloat16 h1 = __float2bfloat16(r1 * hh.y);
                    uint32_t hp = (uint32_t)__bfloat16_as_ushort(h0) |
                                  ((uint32_t)__bfloat16_as_ushort(h1) << 16);
                    *(uint32_t*)(smx + 16384 + a_off(m, j))       = hp;
                    *(uint32_t*)(smx + 16384 + a_off(m, 256 + j)) = hp;
                }
            }
        } else {
            #pragma unroll
            for (int f = 0; f < 4; f++) {
                int j = (wid - 8) * 32 + f * 8 + tc;
                #pragma unroll
                for (int half = 0; half < 2; half++) {
                    int m = half * 8 + g;
                    float am = a_sF[par * 16 + m];
                    float u0 = sigf_(acc[f][half * 2 + 0]) * am;
                    float u1 = sigf_(acc[f][half * 2 + 1]) * am;
                    *(float2*)(u_sF + m * HSTRIDE + j) = make_float2(u0, u1);
                }
            }
        }
        __syncthreads();

        // ---- GEMM2: preact_c = gx_c + rh @ Whc'^T
        float acc2[2][4];
        #pragma unroll
        for (int f = 0; f < 2; f++) {
            int nidx = 512 + wid * 16 + f * 8 + tc;
            float2 v0 = *(const float2*)(gxs + g * GXSTRIDE + nidx);
            float2 v1 = *(const float2*)(gxs + (g + 8) * GXSTRIDE + nidx);
            acc2[f][0] = v0.x; acc2[f][1] = v0.y; acc2[f][2] = v1.x; acc2[f][3] = v1.y;
        }
        gemm_frag<2>(a2u, pw2, lane, acc2);

        // ---- update: h += u'*(tanh(pre_c) - h); pool; write h fp32 + A1 bf16
        #pragma unroll
        for (int f = 0; f < 2; f++) {
            int j2 = wid * 16 + f * 8 + tc;
            #pragma unroll
            for (int half = 0; half < 2; half++) {
                int m = half * 8 + g;
                float c0 = tanhf_(acc2[f][half * 2 + 0]);
                float c1 = tanhf_(acc2[f][half * 2 + 1]);
                float2 uu = *(float2*)(u_sF + m * HSTRIDE + j2);
                float2 hh = *(float2*)(h_sF + m * HSTRIDE + j2);
                float hn0 = hh.x + uu.x * (c0 - hh.x);
                float hn1 = hh.y + uu.y * (c1 - hh.y);
                *(float2*)(h_sF + m * HSTRIDE + j2) = make_float2(hn0, hn1);
                int mk = m_sI[par * 16 + m];
                pool[f][half * 2 + 0] = fmaxf(pool[f][half * 2 + 0], mk ? hn0 : 0.0f);
                pool[f][half * 2 + 1] = fmaxf(pool[f][half * 2 + 1], mk ? hn1 : 0.0f);
                __nv_bfloat16 h0 = __float2bfloat16(hn0);
                __nv_bfloat16 h1 = __float2bfloat16(hn1);
                uint32_t hp = (uint32_t)__bfloat16_as_ushort(h0) |
                              ((uint32_t)__bfloat16_as_ushort(h1) << 16);
                *(uint32_t*)(smx + a_off(m, j2))       = hp;
                *(uint32_t*)(smx + a_off(m, 256 + j2)) = hp;
            }
        }
        CP_WAIT0();          // next gx slab landed (no-op at s=199)
        __syncthreads();
    }

    // ---- epilogue: pooled -> u_s, then out = [h_last | pooled @ Wo^T + bo]
    #pragma unroll
    for (int f = 0; f < 2; f++) {
        int j2 = wid * 16 + f * 8 + tc;
        #pragma unroll
        for (int half = 0; half < 2; half++) {
            int m = half * 8 + g;
            *(float2*)(u_sF + m * HSTRIDE + j2) =
                make_float2(pool[f][half * 2 + 0], pool[f][half * 2 + 1]);
        }
    }
    __syncthreads();

    int jc = t & 255;
    int mh = (t >> 8) * 8;     // threads 0-255 -> rows 0-7, 256-511 -> rows 8-15
    #pragma unroll
    for (int m = 0; m < 8; m++)
        out[(size_t)(b0 + mh + m) * 512 + jc] = h_sF[(mh + m) * HSTRIDE + jc];

    float wacc[8];
    #pragma unroll
    for (int m = 0; m < 8; m++) wacc[m] = 0.0f;
    #pragma unroll 4
    for (int k = 0; k < 256; k++) {
        float wv = Wo[jc * 256 + k];
        #pragma unroll
        for (int m = 0; m < 8; m++) wacc[m] += u_sF[(mh + m) * HSTRIDE + k] * wv;
    }
    float bb = bo[jc];
    #pragma unroll
    for (int m = 0; m < 8; m++)
        out[(size_t)(b0 + mh + m) * 512 + 256 + jc] = wacc[m] + bb;
}

// ---------------- launch ------------------------------------------------------
extern "C" void kernel_launch(void* const* d_in, const int* in_sizes, int n_in,
                              void* d_out, int out_size)
{
    const float* hist = (const float*)d_in[0];
    const float* tgt  = (const float*)d_in[1];
    const int*   mask = (const int*)d_in[2];
    const float* Wr   = (const float*)d_in[3];
    const float* br   = (const float*)d_in[4];
    const float* Wu   = (const float*)d_in[5];
    const float* bu   = (const float*)d_in[6];
    const float* Wc   = (const float*)d_in[7];
    const float* bc   = (const float*)d_in[8];
    const float* Wo   = (const float*)d_in[9];
    const float* bo   = (const float*)d_in[10];
    float* out = (float*)d_out;

    cudaFuncSetAttribute(gx_mma_kernel, cudaFuncAttributeMaxDynamicSharedMemorySize,
                         GX_SMEM_BYTES);
    cudaFuncSetAttribute(gru2_kernel, cudaFuncAttributeMaxDynamicSharedMemorySize,
                         GRU_SMEM);

    prepw_kernel<<<2304, 256>>>(Wr, Wu, Wc);
    prepa_kernel<<<51200, 256>>>(hist);
    attn_kernel<<<NB, 256>>>(hist, tgt, mask);
    gx_mma_kernel<<<dim3(6, 1600), 256, GX_SMEM_BYTES>>>(br, bu, bc);
    gru2_kernel<<<64, 512, GRU_SMEM>>>(mask, Wo, bo, out);
}

// round 16
// speedup vs baseline: 3.3072x; 1.2444x over previous
#include <cuda_runtime.h>
#include <cuda_bf16.h>
#include <cstdint>
#include <math.h>

#define NB 1024
#define NS 200
#define NH 256
#define KTOT 768

// ---------------- scratch (device globals; no allocations allowed) ----------
static __device__ float g_att[NB * NS];                        // softmax attention [b][s]
static __device__ float g_gx[(size_t)NS * NB * 768];           // x-part preact [m'=s*1024+b][768]
static __device__ __nv_bfloat16 g_abf[(size_t)NB * NS * KTOT]; // A' = [Ah|Ah|Al] [m][768] (gx)
static __device__ __nv_bfloat16 g_bbf[768 * KTOT];             // B' = [Bh|Bl|Bh] [n][768] (gx)
static __device__ __nv_bfloat16 g_wruf[512 * 512];             // Whru' frag-layout K=512 (16w,F=4)
static __device__ __nv_bfloat16 g_wcf[256 * 512];              // Whc'  frag-layout K=512 (16w,F=2)
static __device__ int g_done[NS];                              // per-s-slab tile counters (24/slab)

__device__ __forceinline__ float sigf_(float x) {
    return __fdividef(1.0f, 1.0f + __expf(-x));
}
__device__ __forceinline__ float tanhf_(float x) {
    return __fdividef(2.0f, 1.0f + __expf(-2.0f * x)) - 1.0f;
}

__device__ __forceinline__ uint32_t smem_u32(const void* p) {
    uint32_t a;
    asm("{ .reg .u64 t; cvta.to.shared.u64 t, %1; cvt.u32.u64 %0, t; }" : "=r"(a) : "l"(p));
    return a;
}

#define CP_ASYNC16(dst, src) \
    asm volatile("cp.async.cg.shared.global [%0], [%1], 16;" :: "r"(dst), "l"(src))
#define CP_COMMIT() asm volatile("cp.async.commit_group;" ::: "memory")
#define CP_WAIT0()  asm volatile("cp.async.wait_group 0;" ::: "memory")
#define CP_WAIT1()  asm volatile("cp.async.wait_group 1;" ::: "memory")

#define LDSM4(r, addr)                                                            \
    asm volatile("ldmatrix.sync.aligned.m8n8.x4.shared.b16 {%0,%1,%2,%3}, [%4];"  \
                 : "=r"((r)[0]), "=r"((r)[1]), "=r"((r)[2]), "=r"((r)[3])         \
                 : "r"(addr))

#define MMA16816(d, a, b0, b1)                                                    \
    asm volatile("mma.sync.aligned.m16n8k16.row.col.f32.bf16.bf16.f32 "           \
                 "{%0,%1,%2,%3}, {%4,%5,%6,%7}, {%8,%9}, {%0,%1,%2,%3};"          \
                 : "+f"((d)[0]), "+f"((d)[1]), "+f"((d)[2]), "+f"((d)[3])         \
                 : "r"((a)[0]), "r"((a)[1]), "r"((a)[2]), "r"((a)[3]),            \
                   "r"(b0), "r"(b1))

// byte offset of weight element (n,k) in per-warp fragment layout
__device__ __forceinline__ uint32_t frag_off(int n, int k, int F, int sshift, int NT2) {
    int w = n >> sshift;
    int f = (n >> 3) & (F - 1);
    int r = n & 7;
    int t2 = k >> 5;
    int th = (k >> 4) & 1;
    int kk = k & 15;
    int lane = (r << 2) | ((kk & 7) >> 1);
    int byte = (th << 3) | (((kk >> 3) & 1) << 2) | ((kk & 1) << 1);
    return (uint32_t)(((((w * F + f) * NT2 + t2) * 32 + lane) << 4) + byte);
}

// swizzled byte offset within a 16x512-bf16 A-tile (1024B rows)
__device__ __forceinline__ uint32_t a_off(int m, int k) {
    int seg = k >> 3;
    int segs = (seg & ~7) | ((seg ^ m) & 7);
    return (uint32_t)(m * 1024 + segs * 16 + (k & 7) * 2);
}

__device__ __forceinline__ void bf16split(float x, __nv_bfloat16& h, __nv_bfloat16& l) {
    h = __float2bfloat16(x);
    l = __float2bfloat16(x - __bfloat162float(h));
}

__device__ __forceinline__ float biasAt(int n, const float* br, const float* bu,
                                        const float* bc) {
    return (n < 256) ? br[n] : (n < 512) ? bu[n - 256] : bc[n - 512];
}

// consumer wait: slab sn fully produced (24 tiles). Single-kernel: producers are
// co-resident CTAs of THIS launch, so this is safe under ncu serialization too.
__device__ __forceinline__ void wait_slab(int sn) {
    if (threadIdx.x == 0) {
        volatile int* dp = (volatile int*)&g_done[sn];
        while (*dp < 24) __nanosleep(64);
        __threadfence();
    }
    __syncthreads();
}

// ---------------- K0a: weight packing ----------------------------------------
__global__ void prepw_kernel(const float* __restrict__ Wr, const float* __restrict__ Wu,
                             const float* __restrict__ Wc)
{
    int idx = blockIdx.x * blockDim.x + threadIdx.x;
    if (idx < 196608) {
        int n = idx >> 8, k = idx & 255;
        float v;
        if (n < 256)      v = Wr[n * 512 + k];
        else if (n < 512) v = Wu[(n - 256) * 512 + k];
        else              v = Wc[(n - 512) * 512 + k];
        __nv_bfloat16 hi, lo; bf16split(v, hi, lo);
        g_bbf[(size_t)n * KTOT + k]       = hi;
        g_bbf[(size_t)n * KTOT + 256 + k] = lo;
        g_bbf[(size_t)n * KTOT + 512 + k] = hi;
    } else if (idx < 196608 + 262144) {
        int e = idx - 196608;
        int n = e >> 9, k = e & 511;
        int kk = k & 255;
        float v = (n < 256) ? Wr[n * 512 + 256 + kk] : Wu[(n - 256) * 512 + 256 + kk];
        __nv_bfloat16 hi, lo; bf16split(v, hi, lo);
        __nv_bfloat16 val = (k < 256) ? hi : lo;
        *(__nv_bfloat16*)((char*)g_wruf + frag_off(n, k, 4, 5, 16)) = val;
    } else if (idx < 196608 + 262144 + 131072) {
        int e = idx - (196608 + 262144);
        int n = e >> 9, k = e & 511;
        int kk = k & 255;
        float v = Wc[n * 512 + 256 + kk];
        __nv_bfloat16 hi, lo; bf16split(v, hi, lo);
        __nv_bfloat16 val = (k < 256) ? hi : lo;
        *(__nv_bfloat16*)((char*)g_wcf + frag_off(n, k, 2, 4, 16)) = val;
    }
}

// ---------------- K0b: hist -> A' = [Ah | Ah | Al] ----------------------------
__global__ void __launch_bounds__(256) prepa_kernel(const float* __restrict__ hist)
{
    size_t i = (size_t)blockIdx.x * 256 + threadIdx.x;
    if (i < NS) g_done[i] = 0;                 // reset slab counters each call
    int m = (int)(i >> 6);
    int kq = ((int)i & 63) * 4;
    float4 v = *(const float4*)(hist + (size_t)m * 256 + kq);
    float x[4] = {v.x, v.y, v.z, v.w};
    __nv_bfloat16 h[4], l[4];
    #pragma unroll
    for (int j = 0; j < 4; j++) bf16split(x[j], h[j], l[j]);
    uint32_t hi01 = (uint32_t)__bfloat16_as_ushort(h[0]) | ((uint32_t)__bfloat16_as_ushort(h[1]) << 16);
    uint32_t hi23 = (uint32_t)__bfloat16_as_ushort(h[2]) | ((uint32_t)__bfloat16_as_ushort(h[3]) << 16);
    uint32_t lo01 = (uint32_t)__bfloat16_as_ushort(l[0]) | ((uint32_t)__bfloat16_as_ushort(l[1]) << 16);
    uint32_t lo23 = (uint32_t)__bfloat16_as_ushort(l[2]) | ((uint32_t)__bfloat16_as_ushort(l[3]) << 16);
    __nv_bfloat16* row = g_abf + (size_t)m * KTOT + kq;
    *(uint2*)(row)       = make_uint2(hi01, hi23);
    *(uint2*)(row + 256) = make_uint2(hi01, hi23);
    *(uint2*)(row + 512) = make_uint2(lo01, lo23);
}

// ---------------- K1: attention softmax --------------------------------------
__global__ void __launch_bounds__(256) attn_kernel(const float* __restrict__ hist,
                                                   const float* __restrict__ tgt,
                                                   const int* __restrict__ mask)
{
    __shared__ float tg[256];
    __shared__ float lg[200];
    __shared__ float red[8];
    int b = blockIdx.x;
    int t = threadIdx.x;
    int lane = t & 31, w = t >> 5;
    tg[t] = tgt[b * 256 + t];
    __syncthreads();
    for (int s = w; s < 200; s += 8) {
        const float* hp = hist + ((size_t)(b * 200 + s)) * 256;
        float acc = 0.0f;
        #pragma unroll
        for (int i = 0; i < 8; i++) acc += hp[lane + 32 * i] * tg[lane + 32 * i];
        #pragma unroll
        for (int o = 16; o > 0; o >>= 1) acc += __shfl_xor_sync(0xffffffffu, acc, o);
        if (lane == 0)
            lg[s] = (mask[b * 200 + s] == 0) ? -1.0e9f : acc * 0.0625f;
    }
    __syncthreads();
    float v = (t < 200) ? lg[t] : -3.0e38f;
    float m = v;
    #pragma unroll
    for (int o = 16; o > 0; o >>= 1) m = fmaxf(m, __shfl_xor_sync(0xffffffffu, m, o));
    if (lane == 0) red[w] = m;
    __syncthreads();
    if (t == 0) {
        float mm = red[0];
        for (int i = 1; i < 8; i++) mm = fmaxf(mm, red[i]);
        red[0] = mm;
    }
    __syncthreads();
    float mx = red[0];
    float e = (t < 200) ? expf(v - mx) : 0.0f;
    __syncthreads();
    float ssum = e;
    #pragma unroll
    for (int o = 16; o > 0; o >>= 1) ssum += __shfl_xor_sync(0xffffffffu, ssum, o);
    if (lane == 0) red[w] = ssum;
    __syncthreads();
    if (t == 0) {
        float tt = 0.0f;
        for (int i = 0; i < 8; i++) tt += red[i];
        red[0] = tt;
    }
    __syncthreads();
    if (t < 200) g_att[b * 200 + t] = e / red[0];
}

// ---------------- fused kernel: gx producer + GRU consumer --------------------
// grid = numSMs, 512 threads, smem 166144 (>114KB -> 1 CTA/SM -> all resident).
// CTAs 0..63: GRU scan (consumer). CTAs 64..: persistent gx GEMM (producer),
// 256x128 tiles in s-slab order, 24 tiles/slab signalled via g_done.
static constexpr int HSTRIDE = 264;             // floats; 264 % 32 == 8
static constexpr int GXSTRIDE = 776;            // floats; 776 % 32 == 8
static constexpr int GRU_H_OFF   = 32768;
static constexpr int GRU_U_OFF   = 49664;
static constexpr int GRU_ATT_OFF = 66560;
static constexpr int GRU_MSK_OFF = 66688;
static constexpr int GRU_GX_OFF  = 66816;
static constexpr int GRU_GX_SLAB = 16 * GXSTRIDE * 4;          // 49664
static constexpr int FUSED_SMEM = GRU_GX_OFF + 2 * GRU_GX_SLAB; // 166144

// K=512 fragment GEMM: acc[F][4] += A(smem,swizzled) x B(global frag layout)
template<int F>
__device__ __forceinline__ void gemm_frag(uint32_t Abase, const char* pw,
                                          int lane, float acc[][4])
{
    uint4 Bb[3][F];
    #pragma unroll
    for (int p = 0; p < 2; p++)
        #pragma unroll
        for (int f = 0; f < F; f++)
            Bb[p][f] = *(const uint4*)(pw + (f * 16 + p) * 512);
    #pragma unroll
    for (int t2 = 0; t2 < 16; t2++) {
        if (t2 < 14) {
            #pragma unroll
            for (int f = 0; f < F; f++)
                Bb[(t2 + 2) % 3][f] = *(const uint4*)(pw + (f * 16 + t2 + 2) * 512);
        }
        #pragma unroll
        for (int th = 0; th < 2; th++) {
            int row = lane & 15;
            int seg = 4 * t2 + 2 * th + (lane >> 4);
            uint32_t aaddr = Abase + (uint32_t)(row * 1024)
                           + (uint32_t)(((seg & ~7) | ((seg ^ row) & 7)) << 4);
            uint32_t a[4];
            LDSM4(a, aaddr);
            #pragma unroll
            for (int f = 0; f < F; f++) {
                if (th == 0) MMA16816(acc[f], a, Bb[t2 % 3][f].x, Bb[t2 % 3][f].y);
                else         MMA16816(acc[f], a, Bb[t2 % 3][f].z, Bb[t2 % 3][f].w);
            }
        }
    }
}

__global__ void __launch_bounds__(512, 1) fused_kernel(
    const int* __restrict__ mask, const float* __restrict__ Wo,
    const float* __restrict__ bo, float* __restrict__ out,
    const float* __restrict__ br, const float* __restrict__ bu,
    const float* __restrict__ bc)
{
    extern __shared__ char smx[];
    int t = threadIdx.x;
    int lane = t & 31, wid = t >> 5;

    if (blockIdx.x >= 64) {
        // =================== gx producer (persistent, 256x128 tiles) =========
        int p = blockIdx.x - 64;
        int NPROD = gridDim.x - 64;
        uint32_t aT = smem_u32(smx);            // A: 2 x 32768
        uint32_t bT = aT + 65536;               // B: 2 x 16384
        int lrow = t >> 3, lc16 = t & 7;
        uint32_t soff[4];
        #pragma unroll
        for (int r = 0; r < 4; r++) {
            uint32_t off = (uint32_t)((lrow + r * 64) * 128 + lc16 * 16);
            off ^= (off >> 3) & 0x70;
            soff[r] = off;
        }
        int wm = (wid >> 2) * 64;
        int wn = (wid & 3) * 32;
        uint32_t aR[4], aX[4], bR[2], bX[2];
        #pragma unroll
        for (int mf = 0; mf < 4; mf++) {
            uint32_t R = (uint32_t)(wm + mf * 16 + (lane & 15)) * 128;
            aR[mf] = R; aX[mf] = (R >> 3) & 0x70;
        }
        #pragma unroll
        for (int nf2 = 0; nf2 < 2; nf2++) {
            uint32_t R = (uint32_t)(wn + nf2 * 16 + (lane & 15)) * 128;
            bR[nf2] = R; bX[nf2] = (R >> 3) & 0x70;
        }
        uint32_t Ckl = ((uint32_t)(lane >> 4)) << 4;
        const size_t ARS = (size_t)200 * KTOT;
        int groupID = lane >> 2, tc = (lane & 3) * 2;

        for (int T = p; T < 4800; T += NPROD) {
            int y = T / 6;
            int n0 = (T - y * 6) * 128;
            int s_id = y >> 2;
            int brow0 = (y & 3) * 256;
            const __nv_bfloat16* gA =
                g_abf + ((size_t)(brow0 + lrow) * 200 + s_id) * KTOT + lc16 * 8;
            const __nv_bfloat16* gB =
                g_bbf + (size_t)(n0 + lrow) * KTOT + lc16 * 8;

            float d[4][4][4];
            #pragma unroll
            for (int i = 0; i < 4; i++)
                #pragma unroll
                for (int j = 0; j < 4; j++)
                    #pragma unroll
                    for (int r = 0; r < 4; r++) d[i][j][r] = 0.0f;

            #pragma unroll
            for (int r = 0; r < 4; r++)
                CP_ASYNC16(aT + soff[r], gA + (size_t)(r * 64) * ARS);
            #pragma unroll
            for (int r = 0; r < 2; r++)
                CP_ASYNC16(bT + soff[r], gB + (size_t)(r * 64) * KTOT);
            CP_COMMIT();

            for (int c = 0; c < 12; c++) {
                int buf = c & 1;
                if (c + 1 < 12) {
                    int kc = (c + 1) * 64;
                    uint32_t ao = (uint32_t)((buf ^ 1) * 32768);
                    uint32_t bo2 = (uint32_t)((buf ^ 1) * 16384);
                    #pragma unroll
                    for (int r = 0; r < 4; r++)
                        CP_ASYNC16(aT + ao + soff[r], gA + (size_t)(r * 64) * ARS + kc);
                    #pragma unroll
                    for (int r = 0; r < 2; r++)
                        CP_ASYNC16(bT + bo2 + soff[r], gB + (size_t)(r * 64) * KTOT + kc);
                    CP_COMMIT();
                    CP_WAIT1();
                } else {
                    CP_WAIT0();
                }
                __syncthreads();
                uint32_t abase = aT + (uint32_t)(buf * 32768);
                uint32_t bbase = bT + (uint32_t)(buf * 16384);
                #pragma unroll
                for (int ks = 0; ks < 4; ks++) {
                    uint32_t C = (uint32_t)(ks * 32) + Ckl;
                    uint32_t a[4][4], bb[2][4];
                    #pragma unroll
                    for (int mf = 0; mf < 4; mf++)
                        LDSM4(a[mf], abase + aR[mf] + (C ^ aX[mf]));
                    #pragma unroll
                    for (int nf2 = 0; nf2 < 2; nf2++)
                        LDSM4(bb[nf2], bbase + bR[nf2] + (C ^ bX[nf2]));
                    #pragma unroll
                    for (int mf = 0; mf < 4; mf++) {
                        #pragma unroll
                        for (int nf = 0; nf < 4; nf++) {
                            uint32_t b0 = bb[nf >> 1][nf & 1];
                            uint32_t b1 = bb[nf >> 1][(nf & 1) + 2];
                            MMA16816(d[mf][nf], a[mf], b0, b1);
                        }
                    }
                }
                __syncthreads();
            }

            // epilogue: bias + contiguous store to g_gx[m'][n]
            #pragma unroll
            for (int mf = 0; mf < 4; mf++) {
                #pragma unroll
                for (int half = 0; half < 2; half++) {
                    int mprime = y * 256 + wm + mf * 16 + groupID + half * 8;
                    float* dst = g_gx + (size_t)mprime * 768 + n0 + wn;
                    #pragma unroll
                    for (int nf = 0; nf < 4; nf++) {
                        int nn = n0 + wn + nf * 8 + tc;
                        float2 bi = make_float2(biasAt(nn, br, bu, bc),
                                                biasAt(nn + 1, br, bu, bc));
                        float2 o = make_float2(d[mf][nf][half * 2 + 0] + bi.x,
                                               d[mf][nf][half * 2 + 1] + bi.y);
                        *(float2*)(dst + nf * 8 + tc) = o;
                    }
                }
            }
            __threadfence();
            __syncthreads();
            if (t == 0) atomicAdd(&g_done[s_id], 1);
        }
        return;
    }

    // =================== GRU scan consumer (64 CTAs x 16 rows) ===============
    uint32_t a1u = smem_u32(smx);
    uint32_t a2u = a1u + 16384;
    float* h_sF = (float*)(smx + GRU_H_OFF);
    float* u_sF = (float*)(smx + GRU_U_OFF);
    float* a_sF = (float*)(smx + GRU_ATT_OFF);   // [2][16] parity-buffered
    int*   m_sI = (int*)(smx + GRU_MSK_OFF);     // [2][16] parity-buffered

    int b0 = blockIdx.x * 16;
    int g = lane >> 2, tc = (lane & 3) * 2;

    const char* pw1 = (const char*)g_wruf + wid * 32768 + lane * 16;  // F=4 slice
    const char* pw2 = (const char*)g_wcf + wid * 16384 + lane * 16;   // F=2 slice

    #pragma unroll
    for (int i = 0; i < 8; i++) ((uint32_t*)smx)[t + i * 512] = 0u;
    for (int i = t; i < 16 * HSTRIDE; i += 512) h_sF[i] = 0.0f;
    if (t < 16) {
        a_sF[t] = g_att[(b0 + t) * NS];
        m_sI[t] = mask[(b0 + t) * NS];
    }
    // prologue: wait for slab 0, then stage it
    wait_slab(0);
    {
        const char* src = (const char*)(g_gx + (size_t)b0 * 768);
        uint32_t dstb = a1u + GRU_GX_OFF;
        #pragma unroll
        for (int rep = 0; rep < 6; rep++) {
            int u = t + rep * 512;
            int row = u / 192, col = u - row * 192;
            CP_ASYNC16(dstb + (uint32_t)(row * (GXSTRIDE * 4) + col * 16),
                       src + row * 3072 + col * 16);
        }
        CP_COMMIT();
        CP_WAIT0();
    }
    float pool[2][4];
    #pragma unroll
    for (int f = 0; f < 2; f++)
        #pragma unroll
        for (int i = 0; i < 4; i++) pool[f][i] = -3.0e38f;
    __syncthreads();

    #pragma unroll 1
    for (int s = 0; s < 200; s++) {
        int par = s & 1, nxt = par ^ 1;
        const float* gxs = (const float*)(smx + GRU_GX_OFF + par * GRU_GX_SLAB);

        float acc[4][4];
        #pragma unroll
        for (int f = 0; f < 4; f++) {
            int nidx = wid * 32 + f * 8 + tc;
            float2 v0 = *(const float2*)(gxs + g * GXSTRIDE + nidx);
            float2 v1 = *(const float2*)(gxs + (g + 8) * GXSTRIDE + nidx);
            acc[f][0] = v0.x; acc[f][1] = v0.y; acc[f][2] = v1.x; acc[f][3] = v1.y;
        }

        if (s + 1 < 200) {
            wait_slab(s + 1);
            const char* src = (const char*)(g_gx + ((size_t)(s + 1) * NB + b0) * 768);
            uint32_t dstb = a1u + GRU_GX_OFF + (uint32_t)(nxt * GRU_GX_SLAB);
            #pragma unroll
            for (int rep = 0; rep < 6; rep++) {
                int u = t + rep * 512;
                int row = u / 192, col = u - row * 192;
                CP_ASYNC16(dstb + (uint32_t)(row * (GXSTRIDE * 4) + col * 16),
                           src + row * 3072 + col * 16);
            }
            CP_COMMIT();
        }

        gemm_frag<4>(a1u, pw1, lane, acc);

        if (t < 16 && s + 1 < 200) {
            a_sF[nxt * 16 + t] = g_att[(b0 + t) * NS + s + 1];
            m_sI[nxt * 16 + t] = mask[(b0 + t) * NS + s + 1];
        }

        if (wid < 8) {
            #pragma unroll
            for (int f = 0; f < 4; f++) {
                int j = wid * 32 + f * 8 + tc;
                #pragma unroll
                for (int half = 0; half < 2; half++) {
                    int m = half * 8 + g;
                    float r0 = sigf_(acc[f][half * 2 + 0]);
                    float r1 = sigf_(acc[f][half * 2 + 1]);
                    float2 hh = *(float2*)(h_sF + m * HSTRIDE + j);
                    __nv_bfloat16 h0 = __float2bfloat16(r0 * hh.x);
                    __nv_bfloat16 h1 = __float2bfloat16(r1 * hh.y);
                    uint32_t hp = (uint32_t)__bfloat16_as_ushort(h0) |
                                  ((uint32_t)__bfloat16_as_ushort(h1) << 16);
                    *(uint32_t*)(smx + 16384 + a_off(m, j))       = hp;
                    *(uint32_t*)(smx + 16384 + a_off(m, 256 + j)) = hp;
                }
            }
        } else {
            #pragma unroll
            for (int f = 0; f < 4; f++) {
                int j = (wid - 8) * 32 + f * 8 + tc;
                #pragma unroll
                for (int half = 0; half < 2; half++) {
                    int m = half * 8 + g;
                    float am = a_sF[par * 16 + m];
                    float u0 = sigf_(acc[f][half * 2 + 0]) * am;
                    float u1 = sigf_(acc[f][half * 2 + 1]) * am;
                    *(float2*)(u_sF + m * HSTRIDE + j) = make_float2(u0, u1);
                }
            }
        }
        __syncthreads();

        float acc2[2][4];
        #pragma unroll
        for (int f = 0; f < 2; f++) {
            int nidx = 512 + wid * 16 + f * 8 + tc;
            float2 v0 = *(const float2*)(gxs + g * GXSTRIDE + nidx);
            float2 v1 = *(const float2*)(gxs + (g + 8) * GXSTRIDE + nidx);
            acc2[f][0] = v0.x; acc2[f][1] = v0.y; acc2[f][2] = v1.x; acc2[f][3] = v1.y;
        }
        gemm_frag<2>(a2u, pw2, lane, acc2);

        #pragma unroll
        for (int f = 0; f < 2; f++) {
            int j2 = wid * 16 + f * 8 + tc;
            #pragma unroll
            for (int half = 0; half < 2; half++) {
                int m = half * 8 + g;
                float c0 = tanhf_(acc2[f][half * 2 + 0]);
                float c1 = tanhf_(acc2[f][half * 2 + 1]);
                float2 uu = *(float2*)(u_sF + m * HSTRIDE + j2);
                float2 hh = *(float2*)(h_sF + m * HSTRIDE + j2);
                float hn0 = hh.x + uu.x * (c0 - hh.x);
                float hn1 = hh.y + uu.y * (c1 - hh.y);
                *(float2*)(h_sF + m * HSTRIDE + j2) = make_float2(hn0, hn1);
                int mk = m_sI[par * 16 + m];
                pool[f][half * 2 + 0] = fmaxf(pool[f][half * 2 + 0], mk ? hn0 : 0.0f);
                pool[f][half * 2 + 1] = fmaxf(pool[f][half * 2 + 1], mk ? hn1 : 0.0f);
                __nv_bfloat16 h0 = __float2bfloat16(hn0);
                __nv_bfloat16 h1 = __float2bfloat16(hn1);
                uint32_t hp = (uint32_t)__bfloat16_as_ushort(h0) |
                              ((uint32_t)__bfloat16_as_ushort(h1) << 16);
                *(uint32_t*)(smx + a_off(m, j2))       = hp;
                *(uint32_t*)(smx + a_off(m, 256 + j2)) = hp;
            }
        }
        CP_WAIT0();
        __syncthreads();
    }

    #pragma unroll
    for (int f = 0; f < 2; f++) {
        int j2 = wid * 16 + f * 8 + tc;
        #pragma unroll
        for (int half = 0; half < 2; half++) {
            int m = half * 8 + g;
            *(float2*)(u_sF + m * HSTRIDE + j2) =
                make_float2(pool[f][half * 2 + 0], pool[f][half * 2 + 1]);
        }
    }
    __syncthreads();

    int jc = t & 255;
    int mh = (t >> 8) * 8;
    #pragma unroll
    for (int m = 0; m < 8; m++)
        out[(size_t)(b0 + mh + m) * 512 + jc] = h_sF[(mh + m) * HSTRIDE + jc];

    float wacc[8];
    #pragma unroll
    for (int m = 0; m < 8; m++) wacc[m] = 0.0f;
    #pragma unroll 4
    for (int k = 0; k < 256; k++) {
        float wv = Wo[jc * 256 + k];
        #pragma unroll
        for (int m = 0; m < 8; m++) wacc[m] += u_sF[(mh + m) * HSTRIDE + k] * wv;
    }
    float bb = bo[jc];
    #pragma unroll
    for (int m = 0; m < 8; m++)
        out[(size_t)(b0 + mh + m) * 512 + 256 + jc] = wacc[m] + bb;
}

// ---------------- launch ------------------------------------------------------
extern "C" void kernel_launch(void* const* d_in, const int* in_sizes, int n_in,
                              void* d_out, int out_size)
{
    const float* hist = (const float*)d_in[0];
    const float* tgt  = (const float*)d_in[1];
    const int*   mask = (const int*)d_in[2];
    const float* Wr   = (const float*)d_in[3];
    const float* br   = (const float*)d_in[4];
    const float* Wu   = (const float*)d_in[5];
    const float* bu   = (const float*)d_in[6];
    const float* Wc   = (const float*)d_in[7];
    const float* bc   = (const float*)d_in[8];
    const float* Wo   = (const float*)d_in[9];
    const float* bo   = (const float*)d_in[10];
    float* out = (float*)d_out;

    static int nsm = 0;
    if (nsm == 0) {
        int dev = 0;
        cudaGetDevice(&dev);
        cudaDeviceGetAttribute(&nsm, cudaDevAttrMultiProcessorCount, dev);
        if (nsm < 66) nsm = 66;   // safety: need >= 2 producer CTAs
        cudaFuncSetAttribute(fused_kernel, cudaFuncAttributeMaxDynamicSharedMemorySize,
                             FUSED_SMEM);
    }

    prepw_kernel<<<2304, 256>>>(Wr, Wu, Wc);
    prepa_kernel<<<51200, 256>>>(hist);
    attn_kernel<<<NB, 256>>>(hist, tgt, mask);
    fused_kernel<<<nsm, 512, FUSED_SMEM>>>(mask, Wo, bo, out, br, bu, bc);
}